// round 13
// baseline (speedup 1.0000x reference)
#include <cuda_runtime.h>
#include <cuda_bf16.h>
#include <cuda_fp16.h>
#include <math.h>
#include <stdint.h>

// ---------------- problem constants ----------------
#define NV 32000
#define NE 512
#define NH 1024
#define NB 32
#define NSEQ 64
#define NSTEP 63
#define NROWS (NSTEP * NB)     // 2016
#define MPAD 2048
#define H3 3072
#define GBLK 128               // persistent blocks (1/SM)
#define LOG2E 1.4426950408889634f

// ---------------- device scratch (static, allowed) ----------------
__device__ __nv_bfloat16 g_Xh[MPAD * NH];
__device__ __nv_bfloat16 g_Wih_h[H3 * NH];
__device__ __half g_outW_f16[(long)NV * NH];   // pre-scaled by log2(e), fp16
__device__ __half g_WH_f16[(long)MPAD * NH];   // wh rows, fp16
__device__ float g_gi[(long)MPAD * H3];        // dead rows stay zero

__device__ __nv_bfloat16 g_Whh_w_bf[H3 * NH];
__device__ __nv_bfloat16 g_Whh_s_bf[H3 * NH];
__device__ __nv_bfloat16 g_Wih_s_bf[H3 * NH];

__device__ float g_word_h[NB * NH];
__device__ float g_sent_h[NB * NH];
__device__ float g_wh[NB * NH];
__device__ __nv_bfloat16 g_word_h_bf[NB * NH];
__device__ __nv_bfloat16 g_sent_h_bf[NB * NH];
__device__ __nv_bfloat16 g_wh_bf[NB * NH];

__device__ float g_sumexp[NROWS];
__device__ float g_tgt[NROWS];          // log2-domain target logit
__device__ float g_eos[NROWS];
__device__ float g_validf[NROWS];
__device__ int   g_nxt[NROWS];
__device__ int   g_rowmap[MPAD];
__device__ int   g_nvalid;
__device__ int   g_eosany[NSTEP];

__device__ volatile int g_arrive[GBLK];
__device__ volatile int g_release;

// ---------------- asm helpers ----------------
__device__ __forceinline__ uint32_t smem_u32(const void* p) {
    return (uint32_t)__cvta_generic_to_shared(p);
}
__device__ __forceinline__ void cp16(void* dst, const void* src) {
    asm volatile("cp.async.ca.shared.global [%0], [%1], 16;\n"
                 :: "r"(smem_u32(dst)), "l"(src));
}
__device__ __forceinline__ void cp_commit() {
    asm volatile("cp.async.commit_group;\n");
}
template <int N>
__device__ __forceinline__ void cp_wait() {
    asm volatile("cp.async.wait_group %0;\n" :: "n"(N));
}
__device__ __forceinline__ void ldm4(uint32_t& r0, uint32_t& r1, uint32_t& r2,
                                     uint32_t& r3, const void* p) {
    asm volatile("ldmatrix.sync.aligned.m8n8.x4.shared.b16 {%0,%1,%2,%3}, [%4];\n"
                 : "=r"(r0), "=r"(r1), "=r"(r2), "=r"(r3) : "r"(smem_u32(p)));
}
__device__ __forceinline__ void ldm2(uint32_t& r0, uint32_t& r1, const void* p) {
    asm volatile("ldmatrix.sync.aligned.m8n8.x2.shared.b16 {%0,%1}, [%2];\n"
                 : "=r"(r0), "=r"(r1) : "r"(smem_u32(p)));
}
__device__ __forceinline__ void mma16816(float* d, const uint32_t* a, const uint32_t* b) {
    asm volatile(
        "mma.sync.aligned.m16n8k16.row.col.f32.bf16.bf16.f32 "
        "{%0,%1,%2,%3}, {%4,%5,%6,%7}, {%8,%9}, {%0,%1,%2,%3};\n"
        : "+f"(d[0]), "+f"(d[1]), "+f"(d[2]), "+f"(d[3])
        : "r"(a[0]), "r"(a[1]), "r"(a[2]), "r"(a[3]), "r"(b[0]), "r"(b[1]));
}
// fp16-accumulate mma: 2x rate on post-Ada tensor cores
__device__ __forceinline__ void mma16816h(uint32_t* d, const uint32_t* a,
                                          const uint32_t* b) {
    asm volatile(
        "mma.sync.aligned.m16n8k16.row.col.f16.f16.f16.f16 "
        "{%0,%1}, {%2,%3,%4,%5}, {%6,%7}, {%0,%1};\n"
        : "+r"(d[0]), "+r"(d[1])
        : "r"(a[0]), "r"(a[1]), "r"(a[2]), "r"(a[3]), "r"(b[0]), "r"(b[1]));
}
// exp2 of two packed values in one MUFU op
__device__ __forceinline__ float exp2_pair(float c0, float c1) {
    uint32_t ph, eh;
    asm("cvt.rn.f16x2.f32 %0, %1, %2;" : "=r"(ph) : "f"(c1), "f"(c0));
    asm("ex2.approx.f16x2 %0, %1;" : "=r"(eh) : "r"(ph));
    __half2 hh = *reinterpret_cast<__half2*>(&eh);
    float2 ef = __half22float2(hh);
    return ef.x + ef.y;
}

// ---------------- prologue (misc init + rowmap/eosany fused) ----------------
#define NBLK_MISC ((NB * NH + NROWS + 255) / 256)

__global__ void prologue_misc(const float* __restrict__ sent_state,
                              const int* __restrict__ targets,
                              const int* __restrict__ targets_len) {
    if (blockIdx.x == NBLK_MISC) {
        __shared__ int base[NB + 1];
        int tid = threadIdx.x;
        if (tid <= GBLK) {
            if (tid < GBLK) g_arrive[tid] = 0;
            else            g_release = 0;
        }
        if (tid == 0) {
            int acc = 0;
            for (int b = 0; b < NB; b++) {
                base[b] = acc;
                int len = targets_len[b];
                int cnt = len - 1;
                if (cnt < 0) cnt = 0;
                if (cnt > NSTEP) cnt = NSTEP;
                acc += cnt;
            }
            base[NB] = acc;
            g_nvalid = acc;
        }
        __syncthreads();
        for (int i = tid; i < MPAD; i += 256) g_rowmap[i] = 0;
        for (int s = tid; s < NSTEP; s += 256) {
            int any = 0;
            for (int b = 0; b < NB; b++)
                any |= (targets[b * NSEQ + s + 1] == 1);
            g_eosany[s] = any;
        }
        __syncthreads();
        for (int b = 0; b < NB; b++) {
            int b0 = base[b], cnt = base[b + 1] - b0;
            for (int i = tid; i < cnt; i += 256)
                g_rowmap[b0 + i] = i * NB + b;
        }
        return;
    }
    int idx = blockIdx.x * 256 + threadIdx.x;
    if (idx < NB * NH) {
        float v = sent_state[idx];
        g_word_h[idx] = v;
        g_sent_h[idx] = v;
        __nv_bfloat16 vb = __float2bfloat16(v);
        g_word_h_bf[idx] = vb;
        g_sent_h_bf[idx] = vb;
    } else if (idx < NB * NH + NROWS) {
        int r = idx - NB * NH;
        int i = r >> 5, b = r & 31;
        int nxt = targets[b * NSEQ + i + 1];
        g_nxt[r] = nxt;
        g_eos[r] = (nxt == 1) ? 1.f : 0.f;
        g_validf[r] = (targets_len[b] > (i + 1)) ? 1.f : 0.f;
        g_sumexp[r] = 0.f;
        g_tgt[r] = 0.f;
    }
}

__device__ __forceinline__ uint4 pack8(float4 a, float4 b, float sc) {
    __nv_bfloat16 h[8];
    h[0] = __float2bfloat16(a.x * sc); h[1] = __float2bfloat16(a.y * sc);
    h[2] = __float2bfloat16(a.z * sc); h[3] = __float2bfloat16(a.w * sc);
    h[4] = __float2bfloat16(b.x * sc); h[5] = __float2bfloat16(b.y * sc);
    h[6] = __float2bfloat16(b.z * sc); h[7] = __float2bfloat16(b.w * sc);
    uint4 u;
    uint16_t* s = (uint16_t*)&u;
#pragma unroll
    for (int i = 0; i < 8; i++) s[i] = *(uint16_t*)&h[i];
    return u;
}
__device__ __forceinline__ uint4 pack8h(float4 a, float4 b, float sc) {
    __half h[8];
    h[0] = __float2half_rn(a.x * sc); h[1] = __float2half_rn(a.y * sc);
    h[2] = __float2half_rn(a.z * sc); h[3] = __float2half_rn(a.w * sc);
    h[4] = __float2half_rn(b.x * sc); h[5] = __float2half_rn(b.y * sc);
    h[6] = __float2half_rn(b.z * sc); h[7] = __float2half_rn(b.w * sc);
    uint4 u;
    uint16_t* s = (uint16_t*)&u;
#pragma unroll
    for (int i = 0; i < 8; i++) s[i] = *(uint16_t*)&h[i];
    return u;
}

__global__ void build_X(const int* __restrict__ targets,
                        const int* __restrict__ targets_kws,
                        const float* __restrict__ emb) {
    int t = blockIdx.x * 256 + threadIdx.x;
    int r = t >> 7;
    int c0 = (t & 127) * 8;
    uint4 u;
    if (r < NROWS) {
        int i = r >> 5, b = r & 31;
        int tok = (c0 < NE) ? targets_kws[b * NSEQ + i + 1] : targets[b * NSEQ + i];
        const float4* e = (const float4*)(emb + (long)tok * NE + (c0 & (NE - 1)));
        u = pack8(e[0], e[1], 1.f);
    } else {
        u = make_uint4(0, 0, 0, 0);
    }
    *(uint4*)&g_Xh[(long)r * NH + c0] = u;
}

#define RSEG 3145728L
__global__ void conv_all(const float* __restrict__ Wih,
                         const float* __restrict__ whw,
                         const float* __restrict__ whs,
                         const float* __restrict__ wis,
                         const float* __restrict__ outW) {
    long e0 = ((long)blockIdx.x * 256 + threadIdx.x) * 8;
    if (e0 < 4 * RSEG) {
        const float* src; __nv_bfloat16* dst; long off;
        if      (e0 < RSEG)     { src = Wih;  dst = g_Wih_h;    off = e0; }
        else if (e0 < 2 * RSEG) { src = whw;  dst = g_Whh_w_bf; off = e0 - RSEG; }
        else if (e0 < 3 * RSEG) { src = whs;  dst = g_Whh_s_bf; off = e0 - 2 * RSEG; }
        else                    { src = wis;  dst = g_Wih_s_bf; off = e0 - 3 * RSEG; }
        const float4* p = (const float4*)(src + off);
        *(uint4*)(dst + off) = pack8(p[0], p[1], 1.f);
    } else {
        long off = e0 - 4 * RSEG;
        const float4* p = (const float4*)(outW + off);
        *(uint4*)(g_outW_f16 + off) = pack8h(p[0], p[1], LOG2E);
    }
}

// ---------------- bf16 GEMM (gi): C = A[M,K] * B[N,K]^T, compacted rows ----------
#define BK 32
#define PADK 40

__global__ __launch_bounds__(256, 2)
void gemm_gi(const float* __restrict__ bias) {
    const long bm = blockIdx.y, bn = blockIdx.x;
    const int nvalid = g_nvalid;
    if ((int)(bm * 128) >= nvalid) return;

    const __nv_bfloat16* A = g_Xh;
    const __nv_bfloat16* B = g_Wih_h;
    float* C = g_gi;
    const int K = NH, N = H3;

    __shared__ __nv_bfloat16 As[2][128][PADK];
    __shared__ __nv_bfloat16 Bs[2][128][PADK];

    const int tid = threadIdx.x;
    const int lane = tid & 31, wid = tid >> 5;
    const int wm = wid >> 2, wn = wid & 3;
    const int KT = K / BK;

    float acc[4][4][4];
#pragma unroll
    for (int i = 0; i < 4; i++)
#pragma unroll
        for (int j = 0; j < 4; j++)
#pragma unroll
            for (int k = 0; k < 4; k++) acc[i][j][k] = 0.f;

    const int r0 = tid >> 2, kc0 = tid & 3;
    const int r1 = (tid + 256) >> 2;

    const long arow0 = (long)g_rowmap[bm * 128 + r0] * K;
    const long arow1 = (long)g_rowmap[bm * 128 + r1] * K;

    {
        cp16(&As[0][r0][kc0 * 8], A + arow0 + kc0 * 8);
        cp16(&As[0][r1][kc0 * 8], A + arow1 + kc0 * 8);
        cp16(&Bs[0][r0][kc0 * 8], B + (bn * 128 + r0) * (long)K + kc0 * 8);
        cp16(&Bs[0][r1][kc0 * 8], B + (bn * 128 + r1) * (long)K + kc0 * 8);
        cp_commit();
    }

    for (int kt = 0; kt < KT; kt++) {
        int cur = kt & 1;
        if (kt + 1 < KT) {
            int nx = cur ^ 1;
            long ko = (long)(kt + 1) * BK;
            cp16(&As[nx][r0][kc0 * 8], A + arow0 + ko + kc0 * 8);
            cp16(&As[nx][r1][kc0 * 8], A + arow1 + ko + kc0 * 8);
            cp16(&Bs[nx][r0][kc0 * 8], B + (bn * 128 + r0) * (long)K + ko + kc0 * 8);
            cp16(&Bs[nx][r1][kc0 * 8], B + (bn * 128 + r1) * (long)K + ko + kc0 * 8);
            cp_commit();
            cp_wait<1>();
        } else {
            cp_wait<0>();
        }
        __syncthreads();

#pragma unroll
        for (int ks = 0; ks < BK; ks += 16) {
            uint32_t a[4][4];
#pragma unroll
            for (int mt = 0; mt < 4; mt++) {
                int row = wm * 64 + mt * 16 + (lane & 15);
                int col = ks + ((lane >> 4) << 3);
                ldm4(a[mt][0], a[mt][1], a[mt][2], a[mt][3], &As[cur][row][col]);
            }
            uint32_t b[4][2];
#pragma unroll
            for (int np = 0; np < 2; np++) {
                int n = wn * 32 + np * 16 + ((lane >> 4) << 3) + (lane & 7);
                int col = ks + (((lane >> 3) & 1) << 3);
                uint32_t q0, q1, q2, q3;
                ldm4(q0, q1, q2, q3, &Bs[cur][n][col]);
                b[np * 2][0] = q0; b[np * 2][1] = q1;
                b[np * 2 + 1][0] = q2; b[np * 2 + 1][1] = q3;
            }
#pragma unroll
            for (int mt = 0; mt < 4; mt++)
#pragma unroll
                for (int nt = 0; nt < 4; nt++)
                    mma16816(acc[mt][nt], a[mt], b[nt]);
        }
        __syncthreads();
    }

#pragma unroll
    for (int mt = 0; mt < 4; mt++)
#pragma unroll
        for (int ri = 0; ri < 2; ri++) {
            int grow_c = (int)(bm * 128) + wm * 64 + mt * 16 + (lane >> 2) + ri * 8;
            if (grow_c >= nvalid) continue;
            long orig = g_rowmap[grow_c];
#pragma unroll
            for (int nt = 0; nt < 4; nt++) {
                int gc = (int)(bn * 128) + wn * 32 + nt * 8 + ((lane & 3) << 1);
                float v0 = acc[mt][nt][ri * 2 + 0] + bias[gc];
                float v1 = acc[mt][nt][ri * 2 + 1] + bias[gc + 1];
                *(float2*)&C[orig * N + gc] = make_float2(v0, v1);
            }
        }
}

// ---------------- fp16-accumulate vocab GEMM + fused exp2 epilogue ----------------
__global__ __launch_bounds__(256, 2)
void gemm_vocab(const float* __restrict__ bias) {
    const long bm = blockIdx.x, bn = blockIdx.y;   // bm fastest: B-tile L2 reuse
    const int nvalid = g_nvalid;
    if ((int)(bm * 128) >= nvalid) return;

    const __half* A = g_WH_f16;
    const __half* B = g_outW_f16;
    const int K = NH;

    __shared__ __half As[2][128][PADK];
    __shared__ __half Bs[2][128][PADK];
    __shared__ float redbuf[128][4];

    const int tid = threadIdx.x;
    const int lane = tid & 31, wid = tid >> 5;
    const int wm = wid >> 2, wn = wid & 3;
    const int KT = K / BK;

    uint32_t acc[4][4][2];
#pragma unroll
    for (int i = 0; i < 4; i++)
#pragma unroll
        for (int j = 0; j < 4; j++) { acc[i][j][0] = 0u; acc[i][j][1] = 0u; }

    const int r0 = tid >> 2, kc0 = tid & 3;
    const int r1 = (tid + 256) >> 2;

    const long arow0 = (long)g_rowmap[bm * 128 + r0] * K;
    const long arow1 = (long)g_rowmap[bm * 128 + r1] * K;

    {
        cp16(&As[0][r0][kc0 * 8], A + arow0 + kc0 * 8);
        cp16(&As[0][r1][kc0 * 8], A + arow1 + kc0 * 8);
        cp16(&Bs[0][r0][kc0 * 8], B + (bn * 128 + r0) * (long)K + kc0 * 8);
        cp16(&Bs[0][r1][kc0 * 8], B + (bn * 128 + r1) * (long)K + kc0 * 8);
        cp_commit();
    }

    for (int kt = 0; kt < KT; kt++) {
        int cur = kt & 1;
        if (kt + 1 < KT) {
            int nx = cur ^ 1;
            long ko = (long)(kt + 1) * BK;
            cp16(&As[nx][r0][kc0 * 8], A + arow0 + ko + kc0 * 8);
            cp16(&As[nx][r1][kc0 * 8], A + arow1 + ko + kc0 * 8);
            cp16(&Bs[nx][r0][kc0 * 8], B + (bn * 128 + r0) * (long)K + ko + kc0 * 8);
            cp16(&Bs[nx][r1][kc0 * 8], B + (bn * 128 + r1) * (long)K + ko + kc0 * 8);
            cp_commit();
            cp_wait<1>();
        } else {
            cp_wait<0>();
        }
        __syncthreads();

#pragma unroll
        for (int ks = 0; ks < BK; ks += 16) {
            uint32_t a[4][4];
#pragma unroll
            for (int mt = 0; mt < 4; mt++) {
                int row = wm * 64 + mt * 16 + (lane & 15);
                int col = ks + ((lane >> 4) << 3);
                ldm4(a[mt][0], a[mt][1], a[mt][2], a[mt][3], &As[cur][row][col]);
            }
            uint32_t b[4][2];
#pragma unroll
            for (int np = 0; np < 2; np++) {
                int n = wn * 32 + np * 16 + ((lane >> 4) << 3) + (lane & 7);
                int col = ks + (((lane >> 3) & 1) << 3);
                uint32_t q0, q1, q2, q3;
                ldm4(q0, q1, q2, q3, &Bs[cur][n][col]);
                b[np * 2][0] = q0; b[np * 2][1] = q1;
                b[np * 2 + 1][0] = q2; b[np * 2 + 1][1] = q3;
            }
#pragma unroll
            for (int mt = 0; mt < 4; mt++)
#pragma unroll
                for (int nt = 0; nt < 4; nt++)
                    mma16816h(acc[mt][nt], a[mt], b[nt]);
        }
        __syncthreads();
    }

    // fused exp2-denominator epilogue (log2 domain)
#pragma unroll
    for (int mt = 0; mt < 4; mt++)
#pragma unroll
        for (int ri = 0; ri < 2; ri++) {
            int rin = wm * 64 + mt * 16 + (lane >> 2) + ri * 8;
            int grow = (int)(bm * 128) + rin;
            int orig = (grow < nvalid) ? g_rowmap[grow] : -1;
            int nxt = (orig >= 0) ? g_nxt[orig] : -1;
            float s = 0.f;
#pragma unroll
            for (int nt = 0; nt < 4; nt++) {
                int gc = (int)(bn * 128) + wn * 32 + nt * 8 + ((lane & 3) << 1);
                __half2 hh = *reinterpret_cast<__half2*>(&acc[mt][nt][ri]);
                float2 f = __half22float2(hh);
                float c0 = f.x + LOG2E * bias[gc];
                float c1 = f.y + LOG2E * bias[gc + 1];
                s += exp2_pair(c0, c1);
                if (gc == nxt)     g_tgt[orig] = c0;
                if (gc + 1 == nxt) g_tgt[orig] = c1;
            }
            s += __shfl_xor_sync(0xffffffffu, s, 1);
            s += __shfl_xor_sync(0xffffffffu, s, 2);
            if ((lane & 3) == 0) redbuf[rin][wn] = s;
        }
    __syncthreads();
    if (tid < 128) {
        int grow = (int)(bm * 128) + tid;
        if (grow < nvalid) {
            float s = redbuf[tid][0] + redbuf[tid][1] + redbuf[tid][2] + redbuf[tid][3];
            atomicAdd(&g_sumexp[g_rowmap[grow]], s);
        }
    }
}

// ---------------- persistent recurrence kernel ----------------
#define SM_W 0
#define SM_H 148608
#define SM_GW 214656
#define SM_GS 217728
#define SM_EOS 220800
#define SM_TOTAL 221056
#define HPITCH 1032
#define WPITCH 1032

__device__ __forceinline__ float sigm(float x) { return 1.f / (1.f + expf(-x)); }

// block-0 parallel gather + broadcast release (R8-measured-good)
__device__ __forceinline__ void gridbar(int bid, int epoch) {
    __syncthreads();
    if (threadIdx.x == 0) {
        __threadfence();
        g_arrive[bid] = epoch;
    }
    if (bid == 0) {
        if (threadIdx.x < GBLK) {
            while (g_arrive[threadIdx.x] < epoch) { }
        }
        __syncthreads();
        if (threadIdx.x == 0) g_release = epoch;
    } else {
        if (threadIdx.x == 0) {
            while (g_release < epoch) { }
        }
    }
    __syncthreads();
}

__device__ __forceinline__ void loadH(__nv_bfloat16* sH, const __nv_bfloat16* src,
                                      int tid) {
    for (int i = tid; i < 32 * 128; i += 256) {
        int r = i >> 7, kc = i & 127;
        cp16(&sH[r * HPITCH + kc * 8], src + r * NH + kc * 8);
    }
    cp_commit();
    cp_wait<0>();
    __syncthreads();
}

__device__ __forceinline__ void mma_matrix(const __nv_bfloat16* sW,
                                           const __nv_bfloat16* sH,
                                           float* sPart, int mat,
                                           int lane, int wid) {
    float acc[3][2][4];
#pragma unroll
    for (int g = 0; g < 3; g++)
#pragma unroll
        for (int m = 0; m < 2; m++)
#pragma unroll
            for (int k = 0; k < 4; k++) acc[g][m][k] = 0.f;

    const int k0 = wid * 128;
#pragma unroll
    for (int ks = 0; ks < 8; ks++) {
        int kc = k0 + ks * 16;
        uint32_t a0[4], a1[4];
        int acol = kc + ((lane >> 4) << 3);
        ldm4(a0[0], a0[1], a0[2], a0[3], &sH[(lane & 15) * HPITCH + acol]);
        ldm4(a1[0], a1[1], a1[2], a1[3], &sH[(16 + (lane & 15)) * HPITCH + acol]);
#pragma unroll
        for (int g = 0; g < 3; g++) {
            uint32_t b[2];
            int bcol = kc + (((lane >> 3) & 1) << 3);
            ldm2(b[0], b[1], &sW[((mat * 3 + g) * 8 + (lane & 7)) * WPITCH + bcol]);
            mma16816(acc[g][0], a0, b);
            mma16816(acc[g][1], a1, b);
        }
    }
    __syncthreads();
#pragma unroll
    for (int g = 0; g < 3; g++)
#pragma unroll
        for (int mf = 0; mf < 2; mf++) {
            int row = mf * 16 + (lane >> 2);
            int cp = (lane & 3) * 2;
            float2* p0 = (float2*)&sPart[(((wid * 3 + g) * 32) + row) * 8 + cp];
            *p0 = make_float2(acc[g][mf][0], acc[g][mf][1]);
            float2* p1 = (float2*)&sPart[(((wid * 3 + g) * 32) + row + 8) * 8 + cp];
            *p1 = make_float2(acc[g][mf][2], acc[g][mf][3]);
        }
    __syncthreads();
}

__global__ __launch_bounds__(256, 1)
void recur_kernel(const float* __restrict__ w_bhh,
                  const float* __restrict__ s_bih,
                  const float* __restrict__ s_bhh) {
    extern __shared__ char smraw[];
    __nv_bfloat16* sW = (__nv_bfloat16*)(smraw + SM_W);
    __nv_bfloat16* sH = (__nv_bfloat16*)(smraw + SM_H);
    float* sPart = (float*)(smraw + SM_H);
    float* sGw = (float*)(smraw + SM_GW);
    float* sGs = (float*)(smraw + SM_GS);
    int* sEos = (int*)(smraw + SM_EOS);

    const int tid = threadIdx.x, bid = blockIdx.x;
    const int lane = tid & 31, wid = tid >> 5;
    const int jj0 = bid * 8;
    const int b = tid >> 3, jj = tid & 7;
    const int col = jj0 + jj;

    for (int s = tid; s < NSTEP; s += 256) sEos[s] = g_eosany[s];

    {
        const __nv_bfloat16* Wsrc[3] = {g_Whh_w_bf, g_Whh_s_bf, g_Wih_s_bf};
        for (int i = tid; i < 9 * 8 * 128; i += 256) {
            int kc = i & 127;
            int r  = (i >> 7) & 7;
            int s  = i >> 10;
            int m = s / 3, g = s - m * 3;
            cp16(&sW[(s * 8 + r) * WPITCH + kc * 8],
                 Wsrc[m] + (long)(g * 1024 + jj0 + r) * NH + kc * 8);
        }
        cp_commit();
        cp_wait<0>();
        __syncthreads();
    }

    int epoch = 0;
    for (int step = 0; step < NSTEP; step++) {
        // prefetch this step's gi preactivations (latency hidden behind loadH)
        const long gbase = (long)(step * NB + b) * H3;
        float pre_r = g_gi[gbase + col];
        float pre_z = g_gi[gbase + NH + col];
        float pre_n = g_gi[gbase + 2 * NH + col];

        const bool fast = (sEos[step] == 0);   // uniform across all blocks

        // ---------- word GRU matvec (always) ----------
        loadH(sH, g_word_h_bf, tid);
        mma_matrix(sW, sH, sPart, 0, lane, wid);
        {
            float s0 = 0.f, s1 = 0.f, s2 = 0.f;
#pragma unroll
            for (int w = 0; w < 8; w++) {
                s0 += sPart[(((w * 3 + 0) * 32) + b) * 8 + jj];
                s1 += sPart[(((w * 3 + 1) * 32) + b) * 8 + jj];
                s2 += sPart[(((w * 3 + 2) * 32) + b) * 8 + jj];
            }
            sGw[(0 * 32 + b) * 8 + jj] = s0;
            sGw[(1 * 32 + b) * 8 + jj] = s1;
            sGw[(2 * 32 + b) * 8 + jj] = s2;
        }
        __syncthreads();

        if (fast) {
            // no EOS anywhere this step: new_word = wh, new_sent = sent_h.
            float hr = sGw[(0 * 32 + b) * 8 + jj] + w_bhh[col];
            float hz = sGw[(1 * 32 + b) * 8 + jj] + w_bhh[NH + col];
            float hn = sGw[(2 * 32 + b) * 8 + jj] + w_bhh[2 * NH + col];
            float h = g_word_h[b * NH + col];
            float r = sigm(pre_r + hr);
            float z = sigm(pre_z + hz);
            float n = tanhf(pre_n + r * hn);
            float wh = (1.f - z) * n + z * h;
            g_word_h[b * NH + col] = wh;
            g_word_h_bf[b * NH + col] = __float2bfloat16(wh);
            g_WH_f16[(long)(step * NB + b) * NH + col] = __float2half_rn(wh);
            gridbar(bid, ++epoch);
            continue;
        }

        // ---------- full path (some EOS in batch) ----------
        loadH(sH, g_sent_h_bf, tid);
        mma_matrix(sW, sH, sPart, 1, lane, wid);
        {
            float s0 = 0.f, s1 = 0.f, s2 = 0.f;
#pragma unroll
            for (int w = 0; w < 8; w++) {
                s0 += sPart[(((w * 3 + 0) * 32) + b) * 8 + jj];
                s1 += sPart[(((w * 3 + 1) * 32) + b) * 8 + jj];
                s2 += sPart[(((w * 3 + 2) * 32) + b) * 8 + jj];
            }
            sGs[(0 * 32 + b) * 8 + jj] = s0 + s_bhh[col];
            sGs[(1 * 32 + b) * 8 + jj] = s1 + s_bhh[NH + col];
            sGs[(2 * 32 + b) * 8 + jj] = s2 + s_bhh[2 * NH + col];

            float hr = sGw[(0 * 32 + b) * 8 + jj] + w_bhh[col];
            float hz = sGw[(1 * 32 + b) * 8 + jj] + w_bhh[NH + col];
            float hn = sGw[(2 * 32 + b) * 8 + jj] + w_bhh[2 * NH + col];
            float h = g_word_h[b * NH + col];
            float r = sigm(pre_r + hr);
            float z = sigm(pre_z + hz);
            float n = tanhf(pre_n + r * hn);
            float wh = (1.f - z) * n + z * h;
            g_wh[b * NH + col] = wh;
            g_wh_bf[b * NH + col] = __float2bfloat16(wh);
            g_WH_f16[(long)(step * NB + b) * NH + col] = __float2half_rn(wh);
        }
        gridbar(bid, ++epoch);

        loadH(sH, g_wh_bf, tid);
        mma_matrix(sW, sH, sPart, 2, lane, wid);
        {
            float s0 = 0.f, s1 = 0.f, s2 = 0.f;
#pragma unroll
            for (int w = 0; w < 8; w++) {
                s0 += sPart[(((w * 3 + 0) * 32) + b) * 8 + jj];
                s1 += sPart[(((w * 3 + 1) * 32) + b) * 8 + jj];
                s2 += sPart[(((w * 3 + 2) * 32) + b) * 8 + jj];
            }
            float ir = s0 + s_bih[col];
            float iz = s1 + s_bih[NH + col];
            float in_ = s2 + s_bih[2 * NH + col];
            float hr = sGs[(0 * 32 + b) * 8 + jj];
            float hz = sGs[(1 * 32 + b) * 8 + jj];
            float hn = sGs[(2 * 32 + b) * 8 + jj];
            float hs = g_sent_h[b * NH + col];
            float r = sigm(ir + hr);
            float z = sigm(iz + hz);
            float n = tanhf(in_ + r * hn);
            float tmp = (1.f - z) * n + z * hs;
            float m = g_eos[step * NB + b];
            float wh = g_wh[b * NH + col];
            float ns = hs + m * (tmp - hs);
            float nw = wh + m * (tmp - wh);
            g_sent_h[b * NH + col] = ns;
            g_word_h[b * NH + col] = nw;
            g_sent_h_bf[b * NH + col] = __float2bfloat16(ns);
            g_word_h_bf[b * NH + col] = __float2bfloat16(nw);
            g_WH_f16[(long)(step * NB + b) * NH + col] = __float2half_rn(nw);
        }
        gridbar(bid, ++epoch);
    }
}

// ---------------- final reduction ----------------
__global__ void final_reduce(float* __restrict__ out) {
    __shared__ double sh[256];
    double s = 0.0;
    for (int r = threadIdx.x; r < NROWS; r += 256) {
        if (g_validf[r] != 0.f) {
            double lse = log((double)g_sumexp[r]);
            s += (double)g_tgt[r] * 0.6931471805599453 - lse;
        }
    }
    sh[threadIdx.x] = s;
    __syncthreads();
    for (int o = 128; o > 0; o >>= 1) {
        if (threadIdx.x < o) sh[threadIdx.x] += sh[threadIdx.x + o];
        __syncthreads();
    }
    if (threadIdx.x == 0) out[0] = (float)(-sh[0]);
}

// ---------------- launch ----------------
extern "C" void kernel_launch(void* const* d_in, const int* in_sizes, int n_in,
                              void* d_out, int out_size) {
    (void)in_sizes; (void)n_in; (void)out_size;
    const int*   targets     = (const int*)d_in[0];
    const int*   targets_kws = (const int*)d_in[1];
    const float* sent_state  = (const float*)d_in[2];
    const int*   targets_len = (const int*)d_in[3];
    const float* emb_W       = (const float*)d_in[4];
    const float* w_Wih       = (const float*)d_in[5];
    const float* w_Whh       = (const float*)d_in[6];
    const float* w_bih       = (const float*)d_in[7];
    const float* w_bhh       = (const float*)d_in[8];
    const float* s_Wih       = (const float*)d_in[9];
    const float* s_Whh       = (const float*)d_in[10];
    const float* s_bih       = (const float*)d_in[11];
    const float* s_bhh       = (const float*)d_in[12];
    const float* out_W       = (const float*)d_in[13];
    const float* out_b       = (const float*)d_in[14];
    float* out = (float*)d_out;

    cudaFuncSetAttribute(recur_kernel,
                         cudaFuncAttributeMaxDynamicSharedMemorySize, SM_TOTAL);

    // prologue (misc init + rowmap/eosany fused: one launch)
    prologue_misc<<<NBLK_MISC + 1, 256>>>(sent_state, targets, targets_len);
    build_X<<<(MPAD * NH / 8) / 256, 256>>>(targets, targets_kws, emb_W);
    conv_all<<<(int)((4 * RSEG + (long)NV * NH) / 8 / 256), 256>>>(
        w_Wih, w_Whh, s_Whh, s_Wih, out_W);

    // gi = X @ Wih^T + bih (bf16), valid rows only (gather/scatter)
    gemm_gi<<<dim3(H3 / 128, MPAD / 128), 256>>>(w_bih);

    // persistent recurrence (63 steps, 1 launch, EOS-aware fast path)
    recur_kernel<<<GBLK, 256, SM_TOTAL>>>(w_bhh, s_bih, s_bhh);

    // fp16-accumulate vocab projection (log2 domain), bm-fastest grid
    gemm_vocab<<<dim3(MPAD / 128, NV / 128), 256>>>(out_b);

    final_reduce<<<1, 256>>>(out);
}

// round 14
// speedup vs baseline: 1.0836x; 1.0836x over previous
#include <cuda_runtime.h>
#include <cuda_bf16.h>
#include <cuda_fp16.h>
#include <math.h>
#include <stdint.h>

// ---------------- problem constants ----------------
#define NV 32000
#define NE 512
#define NH 1024
#define NB 32
#define NSEQ 64
#define NSTEP 63
#define NROWS (NSTEP * NB)     // 2016
#define MPAD 2048
#define H3 3072
#define GBLK 128               // persistent blocks (1/SM)
#define LOG2E 1.4426950408889634f

// ---------------- device scratch (static, allowed) ----------------
__device__ __nv_bfloat16 g_Xh[MPAD * NH];
__device__ __nv_bfloat16 g_Wih_h[H3 * NH];
__device__ __half g_outW_f16[(long)NV * NH];   // pre-scaled by log2(e), fp16
__device__ __half g_WH_f16[(long)MPAD * NH];   // wh rows, fp16
__device__ float g_gi[(long)MPAD * H3];        // dead rows stay zero

__device__ __nv_bfloat16 g_Whh_w_bf[H3 * NH];
__device__ __nv_bfloat16 g_Whh_s_bf[H3 * NH];
__device__ __nv_bfloat16 g_Wih_s_bf[H3 * NH];

__device__ float g_word_h[NB * NH];
__device__ float g_sent_h[NB * NH];
__device__ float g_wh[NB * NH];
__device__ __nv_bfloat16 g_word_h_bf[NB * NH];
__device__ __nv_bfloat16 g_sent_h_bf[NB * NH];
__device__ __nv_bfloat16 g_wh_bf[NB * NH];

__device__ float g_sumexp[NROWS];
__device__ float g_tgt[NROWS];          // log2-domain target logit
__device__ float g_eos[NROWS];
__device__ float g_validf[NROWS];
__device__ int   g_nxt[NROWS];
__device__ int   g_rowmap[MPAD];
__device__ int   g_nvalid;
__device__ int   g_eosany[NSTEP];

__device__ volatile int g_arrive[GBLK];
__device__ volatile int g_release;

// ---------------- asm helpers ----------------
__device__ __forceinline__ uint32_t smem_u32(const void* p) {
    return (uint32_t)__cvta_generic_to_shared(p);
}
__device__ __forceinline__ void cp16(void* dst, const void* src) {
    asm volatile("cp.async.ca.shared.global [%0], [%1], 16;\n"
                 :: "r"(smem_u32(dst)), "l"(src));
}
__device__ __forceinline__ void cp_commit() {
    asm volatile("cp.async.commit_group;\n");
}
template <int N>
__device__ __forceinline__ void cp_wait() {
    asm volatile("cp.async.wait_group %0;\n" :: "n"(N));
}
__device__ __forceinline__ void ldm4(uint32_t& r0, uint32_t& r1, uint32_t& r2,
                                     uint32_t& r3, const void* p) {
    asm volatile("ldmatrix.sync.aligned.m8n8.x4.shared.b16 {%0,%1,%2,%3}, [%4];\n"
                 : "=r"(r0), "=r"(r1), "=r"(r2), "=r"(r3) : "r"(smem_u32(p)));
}
__device__ __forceinline__ void ldm2(uint32_t& r0, uint32_t& r1, const void* p) {
    asm volatile("ldmatrix.sync.aligned.m8n8.x2.shared.b16 {%0,%1}, [%2];\n"
                 : "=r"(r0), "=r"(r1) : "r"(smem_u32(p)));
}
__device__ __forceinline__ void mma16816(float* d, const uint32_t* a, const uint32_t* b) {
    asm volatile(
        "mma.sync.aligned.m16n8k16.row.col.f32.bf16.bf16.f32 "
        "{%0,%1,%2,%3}, {%4,%5,%6,%7}, {%8,%9}, {%0,%1,%2,%3};\n"
        : "+f"(d[0]), "+f"(d[1]), "+f"(d[2]), "+f"(d[3])
        : "r"(a[0]), "r"(a[1]), "r"(a[2]), "r"(a[3]), "r"(b[0]), "r"(b[1]));
}
// fp16-accumulate mma (same issue rate as f32-acc on sm_103; used for register economy)
__device__ __forceinline__ void mma16816h(uint32_t* d, const uint32_t* a,
                                          const uint32_t* b) {
    asm volatile(
        "mma.sync.aligned.m16n8k16.row.col.f16.f16.f16.f16 "
        "{%0,%1}, {%2,%3,%4,%5}, {%6,%7}, {%0,%1};\n"
        : "+r"(d[0]), "+r"(d[1])
        : "r"(a[0]), "r"(a[1]), "r"(a[2]), "r"(a[3]), "r"(b[0]), "r"(b[1]));
}
// exp2 of two packed values in one MUFU op
__device__ __forceinline__ float exp2_pair(float c0, float c1) {
    uint32_t ph, eh;
    asm("cvt.rn.f16x2.f32 %0, %1, %2;" : "=r"(ph) : "f"(c1), "f"(c0));
    asm("ex2.approx.f16x2 %0, %1;" : "=r"(eh) : "r"(ph));
    __half2 hh = *reinterpret_cast<__half2*>(&eh);
    float2 ef = __half22float2(hh);
    return ef.x + ef.y;
}

// ---------------- prologue (misc init + rowmap/eosany fused) ----------------
#define NBLK_MISC ((NB * NH + NROWS + 255) / 256)

__global__ void prologue_misc(const float* __restrict__ sent_state,
                              const int* __restrict__ targets,
                              const int* __restrict__ targets_len) {
    if (blockIdx.x == NBLK_MISC) {
        __shared__ int base[NB + 1];
        int tid = threadIdx.x;
        if (tid <= GBLK) {
            if (tid < GBLK) g_arrive[tid] = 0;
            else            g_release = 0;
        }
        if (tid == 0) {
            int acc = 0;
            for (int b = 0; b < NB; b++) {
                base[b] = acc;
                int len = targets_len[b];
                int cnt = len - 1;
                if (cnt < 0) cnt = 0;
                if (cnt > NSTEP) cnt = NSTEP;
                acc += cnt;
            }
            base[NB] = acc;
            g_nvalid = acc;
        }
        __syncthreads();
        for (int i = tid; i < MPAD; i += 256) g_rowmap[i] = 0;
        for (int s = tid; s < NSTEP; s += 256) {
            int any = 0;
            for (int b = 0; b < NB; b++)
                any |= (targets[b * NSEQ + s + 1] == 1);
            g_eosany[s] = any;
        }
        __syncthreads();
        for (int b = 0; b < NB; b++) {
            int b0 = base[b], cnt = base[b + 1] - b0;
            for (int i = tid; i < cnt; i += 256)
                g_rowmap[b0 + i] = i * NB + b;
        }
        return;
    }
    int idx = blockIdx.x * 256 + threadIdx.x;
    if (idx < NB * NH) {
        float v = sent_state[idx];
        g_word_h[idx] = v;
        g_sent_h[idx] = v;
        __nv_bfloat16 vb = __float2bfloat16(v);
        g_word_h_bf[idx] = vb;
        g_sent_h_bf[idx] = vb;
    } else if (idx < NB * NH + NROWS) {
        int r = idx - NB * NH;
        int i = r >> 5, b = r & 31;
        int nxt = targets[b * NSEQ + i + 1];
        g_nxt[r] = nxt;
        g_eos[r] = (nxt == 1) ? 1.f : 0.f;
        g_validf[r] = (targets_len[b] > (i + 1)) ? 1.f : 0.f;
        g_sumexp[r] = 0.f;
        g_tgt[r] = 0.f;
    }
}

__device__ __forceinline__ uint4 pack8(float4 a, float4 b, float sc) {
    __nv_bfloat16 h[8];
    h[0] = __float2bfloat16(a.x * sc); h[1] = __float2bfloat16(a.y * sc);
    h[2] = __float2bfloat16(a.z * sc); h[3] = __float2bfloat16(a.w * sc);
    h[4] = __float2bfloat16(b.x * sc); h[5] = __float2bfloat16(b.y * sc);
    h[6] = __float2bfloat16(b.z * sc); h[7] = __float2bfloat16(b.w * sc);
    uint4 u;
    uint16_t* s = (uint16_t*)&u;
#pragma unroll
    for (int i = 0; i < 8; i++) s[i] = *(uint16_t*)&h[i];
    return u;
}
__device__ __forceinline__ uint4 pack8h(float4 a, float4 b, float sc) {
    __half h[8];
    h[0] = __float2half_rn(a.x * sc); h[1] = __float2half_rn(a.y * sc);
    h[2] = __float2half_rn(a.z * sc); h[3] = __float2half_rn(a.w * sc);
    h[4] = __float2half_rn(b.x * sc); h[5] = __float2half_rn(b.y * sc);
    h[6] = __float2half_rn(b.z * sc); h[7] = __float2half_rn(b.w * sc);
    uint4 u;
    uint16_t* s = (uint16_t*)&u;
#pragma unroll
    for (int i = 0; i < 8; i++) s[i] = *(uint16_t*)&h[i];
    return u;
}

__global__ void build_X(const int* __restrict__ targets,
                        const int* __restrict__ targets_kws,
                        const float* __restrict__ emb) {
    int t = blockIdx.x * 256 + threadIdx.x;
    int r = t >> 7;
    int c0 = (t & 127) * 8;
    uint4 u;
    if (r < NROWS) {
        int i = r >> 5, b = r & 31;
        int tok = (c0 < NE) ? targets_kws[b * NSEQ + i + 1] : targets[b * NSEQ + i];
        const float4* e = (const float4*)(emb + (long)tok * NE + (c0 & (NE - 1)));
        u = pack8(e[0], e[1], 1.f);
    } else {
        u = make_uint4(0, 0, 0, 0);
    }
    *(uint4*)&g_Xh[(long)r * NH + c0] = u;
}

#define RSEG 3145728L
__global__ void conv_all(const float* __restrict__ Wih,
                         const float* __restrict__ whw,
                         const float* __restrict__ whs,
                         const float* __restrict__ wis,
                         const float* __restrict__ outW) {
    long e0 = ((long)blockIdx.x * 256 + threadIdx.x) * 8;
    if (e0 < 4 * RSEG) {
        const float* src; __nv_bfloat16* dst; long off;
        if      (e0 < RSEG)     { src = Wih;  dst = g_Wih_h;    off = e0; }
        else if (e0 < 2 * RSEG) { src = whw;  dst = g_Whh_w_bf; off = e0 - RSEG; }
        else if (e0 < 3 * RSEG) { src = whs;  dst = g_Whh_s_bf; off = e0 - 2 * RSEG; }
        else                    { src = wis;  dst = g_Wih_s_bf; off = e0 - 3 * RSEG; }
        const float4* p = (const float4*)(src + off);
        *(uint4*)(dst + off) = pack8(p[0], p[1], 1.f);
    } else {
        long off = e0 - 4 * RSEG;
        const float4* p = (const float4*)(outW + off);
        *(uint4*)(g_outW_f16 + off) = pack8h(p[0], p[1], LOG2E);
    }
}

// ---------------- bf16 GEMM (gi): C = A[M,K] * B[N,K]^T, compacted rows ----------
#define BK 32
#define PADK 40

__global__ __launch_bounds__(256, 2)
void gemm_gi(const float* __restrict__ bias) {
    const long bm = blockIdx.y, bn = blockIdx.x;
    const int nvalid = g_nvalid;
    if ((int)(bm * 128) >= nvalid) return;

    const __nv_bfloat16* A = g_Xh;
    const __nv_bfloat16* B = g_Wih_h;
    float* C = g_gi;
    const int K = NH, N = H3;

    __shared__ __nv_bfloat16 As[2][128][PADK];
    __shared__ __nv_bfloat16 Bs[2][128][PADK];

    const int tid = threadIdx.x;
    const int lane = tid & 31, wid = tid >> 5;
    const int wm = wid >> 2, wn = wid & 3;
    const int KT = K / BK;

    float acc[4][4][4];
#pragma unroll
    for (int i = 0; i < 4; i++)
#pragma unroll
        for (int j = 0; j < 4; j++)
#pragma unroll
            for (int k = 0; k < 4; k++) acc[i][j][k] = 0.f;

    const int r0 = tid >> 2, kc0 = tid & 3;
    const int r1 = (tid + 256) >> 2;

    const long arow0 = (long)g_rowmap[bm * 128 + r0] * K;
    const long arow1 = (long)g_rowmap[bm * 128 + r1] * K;

    {
        cp16(&As[0][r0][kc0 * 8], A + arow0 + kc0 * 8);
        cp16(&As[0][r1][kc0 * 8], A + arow1 + kc0 * 8);
        cp16(&Bs[0][r0][kc0 * 8], B + (bn * 128 + r0) * (long)K + kc0 * 8);
        cp16(&Bs[0][r1][kc0 * 8], B + (bn * 128 + r1) * (long)K + kc0 * 8);
        cp_commit();
    }

    for (int kt = 0; kt < KT; kt++) {
        int cur = kt & 1;
        if (kt + 1 < KT) {
            int nx = cur ^ 1;
            long ko = (long)(kt + 1) * BK;
            cp16(&As[nx][r0][kc0 * 8], A + arow0 + ko + kc0 * 8);
            cp16(&As[nx][r1][kc0 * 8], A + arow1 + ko + kc0 * 8);
            cp16(&Bs[nx][r0][kc0 * 8], B + (bn * 128 + r0) * (long)K + ko + kc0 * 8);
            cp16(&Bs[nx][r1][kc0 * 8], B + (bn * 128 + r1) * (long)K + ko + kc0 * 8);
            cp_commit();
            cp_wait<1>();
        } else {
            cp_wait<0>();
        }
        __syncthreads();

#pragma unroll
        for (int ks = 0; ks < BK; ks += 16) {
            uint32_t a[4][4];
#pragma unroll
            for (int mt = 0; mt < 4; mt++) {
                int row = wm * 64 + mt * 16 + (lane & 15);
                int col = ks + ((lane >> 4) << 3);
                ldm4(a[mt][0], a[mt][1], a[mt][2], a[mt][3], &As[cur][row][col]);
            }
            uint32_t b[4][2];
#pragma unroll
            for (int np = 0; np < 2; np++) {
                int n = wn * 32 + np * 16 + ((lane >> 4) << 3) + (lane & 7);
                int col = ks + (((lane >> 3) & 1) << 3);
                uint32_t q0, q1, q2, q3;
                ldm4(q0, q1, q2, q3, &Bs[cur][n][col]);
                b[np * 2][0] = q0; b[np * 2][1] = q1;
                b[np * 2 + 1][0] = q2; b[np * 2 + 1][1] = q3;
            }
#pragma unroll
            for (int mt = 0; mt < 4; mt++)
#pragma unroll
                for (int nt = 0; nt < 4; nt++)
                    mma16816(acc[mt][nt], a[mt], b[nt]);
        }
        __syncthreads();
    }

#pragma unroll
    for (int mt = 0; mt < 4; mt++)
#pragma unroll
        for (int ri = 0; ri < 2; ri++) {
            int grow_c = (int)(bm * 128) + wm * 64 + mt * 16 + (lane >> 2) + ri * 8;
            if (grow_c >= nvalid) continue;
            long orig = g_rowmap[grow_c];
#pragma unroll
            for (int nt = 0; nt < 4; nt++) {
                int gc = (int)(bn * 128) + wn * 32 + nt * 8 + ((lane & 3) << 1);
                float v0 = acc[mt][nt][ri * 2 + 0] + bias[gc];
                float v1 = acc[mt][nt][ri * 2 + 1] + bias[gc + 1];
                *(float2*)&C[orig * N + gc] = make_float2(v0, v1);
            }
        }
}

// ---------------- vocab GEMM: 128M x 256N tiles, f16 acc, fused exp2 epilogue ----
// dynamic smem: A [2][128][40] half (20480 B) | B [2][256][40] half (40960 B)
//             | redbuf [128][4] float (2048 B)  -> total 63488 B
#define VSM_A 0
#define VSM_B 20480
#define VSM_RED 61440
#define VSM_TOTAL 63488

__global__ __launch_bounds__(256, 2)
void gemm_vocab(const float* __restrict__ bias) {
    const long bm = blockIdx.x, bn = blockIdx.y;   // bm fastest: B-tile L2 reuse
    const int nvalid = g_nvalid;
    if ((int)(bm * 128) >= nvalid) return;

    extern __shared__ char dynsm[];
    __half* sA = (__half*)(dynsm + VSM_A);       // pitch 40
    __half* sB = (__half*)(dynsm + VSM_B);       // pitch 40
    float* redbuf = (float*)(dynsm + VSM_RED);   // [128][4]

    const __half* A = g_WH_f16;
    const __half* B = g_outW_f16;
    const int K = NH;
    const int KT = K / BK;

    const int tid = threadIdx.x;
    const int lane = tid & 31, wid = tid >> 5;
    const int wm = wid >> 2, wn = wid & 3;

    uint32_t acc[4][8][2];
#pragma unroll
    for (int i = 0; i < 4; i++)
#pragma unroll
        for (int j = 0; j < 8; j++) { acc[i][j][0] = 0u; acc[i][j][1] = 0u; }

    // loader geometry: A -> 2 fixed rows/thread, B -> 4 fixed rows/thread
    const int ar0 = tid >> 2, ar1 = (tid + 256) >> 2;   // 0..63, 64..127
    const int akc = (tid & 3) * 8;                      // half offset
    const long arow0 = (long)g_rowmap[bm * 128 + ar0] * K;
    const long arow1 = (long)g_rowmap[bm * 128 + ar1] * K;
    long browt[4];
#pragma unroll
    for (int t = 0; t < 4; t++)
        browt[t] = (bn * 256 + ((tid + t * 256) >> 2)) * (long)K;

    auto load_stage = [&](int st, long ko) {
        __half* dA = sA + st * (128 * PADK);
        __half* dB = sB + st * (256 * PADK);
        cp16(dA + ar0 * PADK + akc, A + arow0 + ko + akc);
        cp16(dA + ar1 * PADK + akc, A + arow1 + ko + akc);
#pragma unroll
        for (int t = 0; t < 4; t++) {
            int row = (tid + t * 256) >> 2;
            cp16(dB + row * PADK + akc, B + browt[t] + ko + akc);
        }
        cp_commit();
    };

    load_stage(0, 0);

    for (int kt = 0; kt < KT; kt++) {
        int cur = kt & 1;
        if (kt + 1 < KT) {
            load_stage(cur ^ 1, (long)(kt + 1) * BK);
            cp_wait<1>();
        } else {
            cp_wait<0>();
        }
        __syncthreads();

#pragma unroll
        for (int ks = 0; ks < BK; ks += 16) {
            uint32_t a[4][4];
#pragma unroll
            for (int mt = 0; mt < 4; mt++) {
                int row = wm * 64 + mt * 16 + (lane & 15);
                int col = ks + ((lane >> 4) << 3);
                ldm4(a[mt][0], a[mt][1], a[mt][2], a[mt][3],
                     sA + cur * (128 * PADK) + row * PADK + col);
            }
            uint32_t b[8][2];
#pragma unroll
            for (int np = 0; np < 4; np++) {
                int n = wn * 64 + np * 16 + ((lane >> 4) << 3) + (lane & 7);
                int col = ks + (((lane >> 3) & 1) << 3);
                uint32_t q0, q1, q2, q3;
                ldm4(q0, q1, q2, q3, sB + cur * (256 * PADK) + n * PADK + col);
                b[np * 2][0] = q0; b[np * 2][1] = q1;
                b[np * 2 + 1][0] = q2; b[np * 2 + 1][1] = q3;
            }
#pragma unroll
            for (int mt = 0; mt < 4; mt++)
#pragma unroll
                for (int nt = 0; nt < 8; nt++)
                    mma16816h(acc[mt][nt], a[mt], b[nt]);
        }
        __syncthreads();
    }

    // fused exp2-denominator epilogue (log2 domain)
#pragma unroll
    for (int mt = 0; mt < 4; mt++)
#pragma unroll
        for (int ri = 0; ri < 2; ri++) {
            int rin = wm * 64 + mt * 16 + (lane >> 2) + ri * 8;
            int grow = (int)(bm * 128) + rin;
            int orig = (grow < nvalid) ? g_rowmap[grow] : -1;
            int nxt = (orig >= 0) ? g_nxt[orig] : -1;
            float s = 0.f;
#pragma unroll
            for (int nt = 0; nt < 8; nt++) {
                int gc = (int)(bn * 256) + wn * 64 + nt * 8 + ((lane & 3) << 1);
                __half2 hh = *reinterpret_cast<__half2*>(&acc[mt][nt][ri]);
                float2 f = __half22float2(hh);
                float c0 = f.x + LOG2E * bias[gc];
                float c1 = f.y + LOG2E * bias[gc + 1];
                s += exp2_pair(c0, c1);
                if (gc == nxt)     g_tgt[orig] = c0;
                if (gc + 1 == nxt) g_tgt[orig] = c1;
            }
            s += __shfl_xor_sync(0xffffffffu, s, 1);
            s += __shfl_xor_sync(0xffffffffu, s, 2);
            if ((lane & 3) == 0) redbuf[rin * 4 + wn] = s;
        }
    __syncthreads();
    if (tid < 128) {
        int grow = (int)(bm * 128) + tid;
        if (grow < nvalid) {
            float s = redbuf[tid * 4 + 0] + redbuf[tid * 4 + 1] +
                      redbuf[tid * 4 + 2] + redbuf[tid * 4 + 3];
            atomicAdd(&g_sumexp[g_rowmap[grow]], s);
        }
    }
}

// ---------------- persistent recurrence kernel ----------------
#define SM_W 0
#define SM_H 148608
#define SM_GW 214656
#define SM_GS 217728
#define SM_EOS 220800
#define SM_TOTAL 221056
#define HPITCH 1032
#define WPITCH 1032

__device__ __forceinline__ float sigm(float x) { return 1.f / (1.f + expf(-x)); }

// block-0 parallel gather + broadcast release (measured good)
__device__ __forceinline__ void gridbar(int bid, int epoch) {
    __syncthreads();
    if (threadIdx.x == 0) {
        __threadfence();
        g_arrive[bid] = epoch;
    }
    if (bid == 0) {
        if (threadIdx.x < GBLK) {
            while (g_arrive[threadIdx.x] < epoch) { }
        }
        __syncthreads();
        if (threadIdx.x == 0) g_release = epoch;
    } else {
        if (threadIdx.x == 0) {
            while (g_release < epoch) { }
        }
    }
    __syncthreads();
}

__device__ __forceinline__ void loadH(__nv_bfloat16* sH, const __nv_bfloat16* src,
                                      int tid) {
    for (int i = tid; i < 32 * 128; i += 256) {
        int r = i >> 7, kc = i & 127;
        cp16(&sH[r * HPITCH + kc * 8], src + r * NH + kc * 8);
    }
    cp_commit();
    cp_wait<0>();
    __syncthreads();
}

__device__ __forceinline__ void mma_matrix(const __nv_bfloat16* sW,
                                           const __nv_bfloat16* sH,
                                           float* sPart, int mat,
                                           int lane, int wid) {
    float acc[3][2][4];
#pragma unroll
    for (int g = 0; g < 3; g++)
#pragma unroll
        for (int m = 0; m < 2; m++)
#pragma unroll
            for (int k = 0; k < 4; k++) acc[g][m][k] = 0.f;

    const int k0 = wid * 128;
#pragma unroll
    for (int ks = 0; ks < 8; ks++) {
        int kc = k0 + ks * 16;
        uint32_t a0[4], a1[4];
        int acol = kc + ((lane >> 4) << 3);
        ldm4(a0[0], a0[1], a0[2], a0[3], &sH[(lane & 15) * HPITCH + acol]);
        ldm4(a1[0], a1[1], a1[2], a1[3], &sH[(16 + (lane & 15)) * HPITCH + acol]);
#pragma unroll
        for (int g = 0; g < 3; g++) {
            uint32_t b[2];
            int bcol = kc + (((lane >> 3) & 1) << 3);
            ldm2(b[0], b[1], &sW[((mat * 3 + g) * 8 + (lane & 7)) * WPITCH + bcol]);
            mma16816(acc[g][0], a0, b);
            mma16816(acc[g][1], a1, b);
        }
    }
    __syncthreads();
#pragma unroll
    for (int g = 0; g < 3; g++)
#pragma unroll
        for (int mf = 0; mf < 2; mf++) {
            int row = mf * 16 + (lane >> 2);
            int cp = (lane & 3) * 2;
            float2* p0 = (float2*)&sPart[(((wid * 3 + g) * 32) + row) * 8 + cp];
            *p0 = make_float2(acc[g][mf][0], acc[g][mf][1]);
            float2* p1 = (float2*)&sPart[(((wid * 3 + g) * 32) + row + 8) * 8 + cp];
            *p1 = make_float2(acc[g][mf][2], acc[g][mf][3]);
        }
    __syncthreads();
}

__global__ __launch_bounds__(256, 1)
void recur_kernel(const float* __restrict__ w_bhh,
                  const float* __restrict__ s_bih,
                  const float* __restrict__ s_bhh) {
    extern __shared__ char smraw[];
    __nv_bfloat16* sW = (__nv_bfloat16*)(smraw + SM_W);
    __nv_bfloat16* sH = (__nv_bfloat16*)(smraw + SM_H);
    float* sPart = (float*)(smraw + SM_H);
    float* sGw = (float*)(smraw + SM_GW);
    float* sGs = (float*)(smraw + SM_GS);
    int* sEos = (int*)(smraw + SM_EOS);

    const int tid = threadIdx.x, bid = blockIdx.x;
    const int lane = tid & 31, wid = tid >> 5;
    const int jj0 = bid * 8;
    const int b = tid >> 3, jj = tid & 7;
    const int col = jj0 + jj;

    for (int s = tid; s < NSTEP; s += 256) sEos[s] = g_eosany[s];

    {
        const __nv_bfloat16* Wsrc[3] = {g_Whh_w_bf, g_Whh_s_bf, g_Wih_s_bf};
        for (int i = tid; i < 9 * 8 * 128; i += 256) {
            int kc = i & 127;
            int r  = (i >> 7) & 7;
            int s  = i >> 10;
            int m = s / 3, g = s - m * 3;
            cp16(&sW[(s * 8 + r) * WPITCH + kc * 8],
                 Wsrc[m] + (long)(g * 1024 + jj0 + r) * NH + kc * 8);
        }
        cp_commit();
        cp_wait<0>();
        __syncthreads();
    }

    int epoch = 0;
    for (int step = 0; step < NSTEP; step++) {
        const long gbase = (long)(step * NB + b) * H3;
        float pre_r = g_gi[gbase + col];
        float pre_z = g_gi[gbase + NH + col];
        float pre_n = g_gi[gbase + 2 * NH + col];

        const bool fast = (sEos[step] == 0);   // uniform across all blocks

        loadH(sH, g_word_h_bf, tid);
        mma_matrix(sW, sH, sPart, 0, lane, wid);
        {
            float s0 = 0.f, s1 = 0.f, s2 = 0.f;
#pragma unroll
            for (int w = 0; w < 8; w++) {
                s0 += sPart[(((w * 3 + 0) * 32) + b) * 8 + jj];
                s1 += sPart[(((w * 3 + 1) * 32) + b) * 8 + jj];
                s2 += sPart[(((w * 3 + 2) * 32) + b) * 8 + jj];
            }
            sGw[(0 * 32 + b) * 8 + jj] = s0;
            sGw[(1 * 32 + b) * 8 + jj] = s1;
            sGw[(2 * 32 + b) * 8 + jj] = s2;
        }
        __syncthreads();

        if (fast) {
            float hr = sGw[(0 * 32 + b) * 8 + jj] + w_bhh[col];
            float hz = sGw[(1 * 32 + b) * 8 + jj] + w_bhh[NH + col];
            float hn = sGw[(2 * 32 + b) * 8 + jj] + w_bhh[2 * NH + col];
            float h = g_word_h[b * NH + col];
            float r = sigm(pre_r + hr);
            float z = sigm(pre_z + hz);
            float n = tanhf(pre_n + r * hn);
            float wh = (1.f - z) * n + z * h;
            g_word_h[b * NH + col] = wh;
            g_word_h_bf[b * NH + col] = __float2bfloat16(wh);
            g_WH_f16[(long)(step * NB + b) * NH + col] = __float2half_rn(wh);
            gridbar(bid, ++epoch);
            continue;
        }

        loadH(sH, g_sent_h_bf, tid);
        mma_matrix(sW, sH, sPart, 1, lane, wid);
        {
            float s0 = 0.f, s1 = 0.f, s2 = 0.f;
#pragma unroll
            for (int w = 0; w < 8; w++) {
                s0 += sPart[(((w * 3 + 0) * 32) + b) * 8 + jj];
                s1 += sPart[(((w * 3 + 1) * 32) + b) * 8 + jj];
                s2 += sPart[(((w * 3 + 2) * 32) + b) * 8 + jj];
            }
            sGs[(0 * 32 + b) * 8 + jj] = s0 + s_bhh[col];
            sGs[(1 * 32 + b) * 8 + jj] = s1 + s_bhh[NH + col];
            sGs[(2 * 32 + b) * 8 + jj] = s2 + s_bhh[2 * NH + col];

            float hr = sGw[(0 * 32 + b) * 8 + jj] + w_bhh[col];
            float hz = sGw[(1 * 32 + b) * 8 + jj] + w_bhh[NH + col];
            float hn = sGw[(2 * 32 + b) * 8 + jj] + w_bhh[2 * NH + col];
            float h = g_word_h[b * NH + col];
            float r = sigm(pre_r + hr);
            float z = sigm(pre_z + hz);
            float n = tanhf(pre_n + r * hn);
            float wh = (1.f - z) * n + z * h;
            g_wh[b * NH + col] = wh;
            g_wh_bf[b * NH + col] = __float2bfloat16(wh);
            g_WH_f16[(long)(step * NB + b) * NH + col] = __float2half_rn(wh);
        }
        gridbar(bid, ++epoch);

        loadH(sH, g_wh_bf, tid);
        mma_matrix(sW, sH, sPart, 2, lane, wid);
        {
            float s0 = 0.f, s1 = 0.f, s2 = 0.f;
#pragma unroll
            for (int w = 0; w < 8; w++) {
                s0 += sPart[(((w * 3 + 0) * 32) + b) * 8 + jj];
                s1 += sPart[(((w * 3 + 1) * 32) + b) * 8 + jj];
                s2 += sPart[(((w * 3 + 2) * 32) + b) * 8 + jj];
            }
            float ir = s0 + s_bih[col];
            float iz = s1 + s_bih[NH + col];
            float in_ = s2 + s_bih[2 * NH + col];
            float hr = sGs[(0 * 32 + b) * 8 + jj];
            float hz = sGs[(1 * 32 + b) * 8 + jj];
            float hn = sGs[(2 * 32 + b) * 8 + jj];
            float hs = g_sent_h[b * NH + col];
            float r = sigm(ir + hr);
            float z = sigm(iz + hz);
            float n = tanhf(in_ + r * hn);
            float tmp = (1.f - z) * n + z * hs;
            float m = g_eos[step * NB + b];
            float wh = g_wh[b * NH + col];
            float ns = hs + m * (tmp - hs);
            float nw = wh + m * (tmp - wh);
            g_sent_h[b * NH + col] = ns;
            g_word_h[b * NH + col] = nw;
            g_sent_h_bf[b * NH + col] = __float2bfloat16(ns);
            g_word_h_bf[b * NH + col] = __float2bfloat16(nw);
            g_WH_f16[(long)(step * NB + b) * NH + col] = __float2half_rn(nw);
        }
        gridbar(bid, ++epoch);
    }
}

// ---------------- final reduction ----------------
__global__ void final_reduce(float* __restrict__ out) {
    __shared__ double sh[256];
    double s = 0.0;
    for (int r = threadIdx.x; r < NROWS; r += 256) {
        if (g_validf[r] != 0.f) {
            double lse = log((double)g_sumexp[r]);
            s += (double)g_tgt[r] * 0.6931471805599453 - lse;
        }
    }
    sh[threadIdx.x] = s;
    __syncthreads();
    for (int o = 128; o > 0; o >>= 1) {
        if (threadIdx.x < o) sh[threadIdx.x] += sh[threadIdx.x + o];
        __syncthreads();
    }
    if (threadIdx.x == 0) out[0] = (float)(-sh[0]);
}

// ---------------- launch ----------------
extern "C" void kernel_launch(void* const* d_in, const int* in_sizes, int n_in,
                              void* d_out, int out_size) {
    (void)in_sizes; (void)n_in; (void)out_size;
    const int*   targets     = (const int*)d_in[0];
    const int*   targets_kws = (const int*)d_in[1];
    const float* sent_state  = (const float*)d_in[2];
    const int*   targets_len = (const int*)d_in[3];
    const float* emb_W       = (const float*)d_in[4];
    const float* w_Wih       = (const float*)d_in[5];
    const float* w_Whh       = (const float*)d_in[6];
    const float* w_bih       = (const float*)d_in[7];
    const float* w_bhh       = (const float*)d_in[8];
    const float* s_Wih       = (const float*)d_in[9];
    const float* s_Whh       = (const float*)d_in[10];
    const float* s_bih       = (const float*)d_in[11];
    const float* s_bhh       = (const float*)d_in[12];
    const float* out_W       = (const float*)d_in[13];
    const float* out_b       = (const float*)d_in[14];
    float* out = (float*)d_out;

    cudaFuncSetAttribute(recur_kernel,
                         cudaFuncAttributeMaxDynamicSharedMemorySize, SM_TOTAL);
    cudaFuncSetAttribute(gemm_vocab,
                         cudaFuncAttributeMaxDynamicSharedMemorySize, VSM_TOTAL);

    // prologue (misc init + rowmap/eosany fused: one launch)
    prologue_misc<<<NBLK_MISC + 1, 256>>>(sent_state, targets, targets_len);
    build_X<<<(MPAD * NH / 8) / 256, 256>>>(targets, targets_kws, emb_W);
    conv_all<<<(int)((4 * RSEG + (long)NV * NH) / 8 / 256), 256>>>(
        w_Wih, w_Whh, s_Whh, s_Wih, out_W);

    // gi = X @ Wih^T + bih (bf16), valid rows only (gather/scatter)
    gemm_gi<<<dim3(H3 / 128, MPAD / 128), 256>>>(w_bih);

    // persistent recurrence (63 steps, 1 launch, EOS-aware fast path)
    recur_kernel<<<GBLK, 256, SM_TOTAL>>>(w_bhh, s_bih, s_bhh);

    // vocab projection: 128x256 tiles, f16 acc, log2 domain, bm-fastest grid
    gemm_vocab<<<dim3(MPAD / 128, NV / 256), 256, VSM_TOTAL>>>(out_b);

    final_reduce<<<1, 256>>>(out);
}

// round 15
// speedup vs baseline: 1.1154x; 1.0293x over previous
#include <cuda_runtime.h>
#include <cuda_bf16.h>
#include <cuda_fp16.h>
#include <math.h>
#include <stdint.h>

// ---------------- problem constants ----------------
#define NV 32000
#define NE 512
#define NH 1024
#define NB 32
#define NSEQ 64
#define NSTEP 63
#define NROWS (NSTEP * NB)     // 2016
#define MPAD 2048
#define H3 3072
#define GBLK 128               // persistent blocks (1/SM)
#define LOG2E 1.4426950408889634f
#define KP 1056                // padded K (bias folded as extra column)
#define KTV 33                 // KP / 32 chunks for vocab GEMM

// ---------------- device scratch (static, allowed) ----------------
__device__ __nv_bfloat16 g_Xh[MPAD * NH];
__device__ __nv_bfloat16 g_Wih_h[H3 * NH];
__device__ __half g_outW_f16[(long)NV * KP];   // [w*log2e (1024) | bias*log2e | 0...]
__device__ __half g_WH_f16[(long)MPAD * KP];   // [wh (1024) | 1.0 | 0...]
__device__ float g_gi[(long)MPAD * H3];        // dead rows stay zero

__device__ __nv_bfloat16 g_Whh_w_bf[H3 * NH];
__device__ __nv_bfloat16 g_Whh_s_bf[H3 * NH];
__device__ __nv_bfloat16 g_Wih_s_bf[H3 * NH];

__device__ float g_word_h[NB * NH];
__device__ float g_sent_h[NB * NH];
__device__ float g_wh[NB * NH];
__device__ __nv_bfloat16 g_word_h_bf[NB * NH];
__device__ __nv_bfloat16 g_sent_h_bf[NB * NH];
__device__ __nv_bfloat16 g_wh_bf[NB * NH];

__device__ float g_sumexp[NROWS];
__device__ float g_tgt[NROWS];          // log2-domain target logit (incl bias)
__device__ float g_eos[NROWS];
__device__ float g_validf[NROWS];
__device__ int   g_nxt[NROWS];
__device__ int   g_rowmap[MPAD];
__device__ int   g_nvalid;
__device__ int   g_eosany[NSTEP];

__device__ volatile int g_arrive[GBLK];
__device__ volatile int g_release;

// ---------------- asm helpers ----------------
__device__ __forceinline__ uint32_t smem_u32(const void* p) {
    return (uint32_t)__cvta_generic_to_shared(p);
}
__device__ __forceinline__ void cp16(void* dst, const void* src) {
    asm volatile("cp.async.ca.shared.global [%0], [%1], 16;\n"
                 :: "r"(smem_u32(dst)), "l"(src));
}
__device__ __forceinline__ void cp_commit() {
    asm volatile("cp.async.commit_group;\n");
}
template <int N>
__device__ __forceinline__ void cp_wait() {
    asm volatile("cp.async.wait_group %0;\n" :: "n"(N));
}
__device__ __forceinline__ void ldm4(uint32_t& r0, uint32_t& r1, uint32_t& r2,
                                     uint32_t& r3, const void* p) {
    asm volatile("ldmatrix.sync.aligned.m8n8.x4.shared.b16 {%0,%1,%2,%3}, [%4];\n"
                 : "=r"(r0), "=r"(r1), "=r"(r2), "=r"(r3) : "r"(smem_u32(p)));
}
__device__ __forceinline__ void ldm2(uint32_t& r0, uint32_t& r1, const void* p) {
    asm volatile("ldmatrix.sync.aligned.m8n8.x2.shared.b16 {%0,%1}, [%2];\n"
                 : "=r"(r0), "=r"(r1) : "r"(smem_u32(p)));
}
__device__ __forceinline__ void mma16816(float* d, const uint32_t* a, const uint32_t* b) {
    asm volatile(
        "mma.sync.aligned.m16n8k16.row.col.f32.bf16.bf16.f32 "
        "{%0,%1,%2,%3}, {%4,%5,%6,%7}, {%8,%9}, {%0,%1,%2,%3};\n"
        : "+f"(d[0]), "+f"(d[1]), "+f"(d[2]), "+f"(d[3])
        : "r"(a[0]), "r"(a[1]), "r"(a[2]), "r"(a[3]), "r"(b[0]), "r"(b[1]));
}
// fp16-accumulate mma (same issue rate as f32-acc on sm_103; register economy)
__device__ __forceinline__ void mma16816h(uint32_t* d, const uint32_t* a,
                                          const uint32_t* b) {
    asm volatile(
        "mma.sync.aligned.m16n8k16.row.col.f16.f16.f16.f16 "
        "{%0,%1}, {%2,%3,%4,%5}, {%6,%7}, {%0,%1};\n"
        : "+r"(d[0]), "+r"(d[1])
        : "r"(a[0]), "r"(a[1]), "r"(a[2]), "r"(a[3]), "r"(b[0]), "r"(b[1]));
}

// ---------------- prologue (misc init + rowmap/eosany + WH pad fused) ----------
#define NBLK_MISC ((NB * NH + NROWS + MPAD * 4 + 255) / 256)

__global__ void prologue_misc(const float* __restrict__ sent_state,
                              const int* __restrict__ targets,
                              const int* __restrict__ targets_len) {
    if (blockIdx.x == NBLK_MISC) {
        __shared__ int base[NB + 1];
        int tid = threadIdx.x;
        if (tid <= GBLK) {
            if (tid < GBLK) g_arrive[tid] = 0;
            else            g_release = 0;
        }
        if (tid == 0) {
            int acc = 0;
            for (int b = 0; b < NB; b++) {
                base[b] = acc;
                int len = targets_len[b];
                int cnt = len - 1;
                if (cnt < 0) cnt = 0;
                if (cnt > NSTEP) cnt = NSTEP;
                acc += cnt;
            }
            base[NB] = acc;
            g_nvalid = acc;
        }
        __syncthreads();
        for (int i = tid; i < MPAD; i += 256) g_rowmap[i] = 0;
        for (int s = tid; s < NSTEP; s += 256) {
            int any = 0;
            for (int b = 0; b < NB; b++)
                any |= (targets[b * NSEQ + s + 1] == 1);
            g_eosany[s] = any;
        }
        __syncthreads();
        for (int b = 0; b < NB; b++) {
            int b0 = base[b], cnt = base[b + 1] - b0;
            for (int i = tid; i < cnt; i += 256)
                g_rowmap[b0 + i] = i * NB + b;
        }
        return;
    }
    int idx = blockIdx.x * 256 + threadIdx.x;
    if (idx < NB * NH) {
        float v = sent_state[idx];
        g_word_h[idx] = v;
        g_sent_h[idx] = v;
        __nv_bfloat16 vb = __float2bfloat16(v);
        g_word_h_bf[idx] = vb;
        g_sent_h_bf[idx] = vb;
    } else if (idx < NB * NH + NROWS) {
        int r = idx - NB * NH;
        int i = r >> 5, b = r & 31;
        int nxt = targets[b * NSEQ + i + 1];
        g_nxt[r] = nxt;
        g_eos[r] = (nxt == 1) ? 1.f : 0.f;
        g_validf[r] = (targets_len[b] > (i + 1)) ? 1.f : 0.f;
        g_sumexp[r] = 0.f;
        g_tgt[r] = 0.f;
    } else if (idx < NB * NH + NROWS + MPAD * 4) {
        // WH pad columns [1024..1056): first = 1.0h (bias row), rest 0
        int k = idx - NB * NH - NROWS;
        int row = k >> 2, c = k & 3;
        uint4 u = make_uint4(0, 0, 0, 0);
        if (c == 0) {
            __half one = __float2half(1.f);
            u.x = (uint32_t)(*(uint16_t*)&one);
        }
        *(uint4*)&g_WH_f16[(long)row * KP + 1024 + c * 8] = u;
    }
}

__device__ __forceinline__ uint4 pack8(float4 a, float4 b, float sc) {
    __nv_bfloat16 h[8];
    h[0] = __float2bfloat16(a.x * sc); h[1] = __float2bfloat16(a.y * sc);
    h[2] = __float2bfloat16(a.z * sc); h[3] = __float2bfloat16(a.w * sc);
    h[4] = __float2bfloat16(b.x * sc); h[5] = __float2bfloat16(b.y * sc);
    h[6] = __float2bfloat16(b.z * sc); h[7] = __float2bfloat16(b.w * sc);
    uint4 u;
    uint16_t* s = (uint16_t*)&u;
#pragma unroll
    for (int i = 0; i < 8; i++) s[i] = *(uint16_t*)&h[i];
    return u;
}
__device__ __forceinline__ uint4 pack8h(float4 a, float4 b, float sc) {
    __half h[8];
    h[0] = __float2half_rn(a.x * sc); h[1] = __float2half_rn(a.y * sc);
    h[2] = __float2half_rn(a.z * sc); h[3] = __float2half_rn(a.w * sc);
    h[4] = __float2half_rn(b.x * sc); h[5] = __float2half_rn(b.y * sc);
    h[6] = __float2half_rn(b.z * sc); h[7] = __float2half_rn(b.w * sc);
    uint4 u;
    uint16_t* s = (uint16_t*)&u;
#pragma unroll
    for (int i = 0; i < 8; i++) s[i] = *(uint16_t*)&h[i];
    return u;
}

__global__ void build_X(const int* __restrict__ targets,
                        const int* __restrict__ targets_kws,
                        const float* __restrict__ emb) {
    int t = blockIdx.x * 256 + threadIdx.x;
    int r = t >> 7;
    int c0 = (t & 127) * 8;
    uint4 u;
    if (r < NROWS) {
        int i = r >> 5, b = r & 31;
        int tok = (c0 < NE) ? targets_kws[b * NSEQ + i + 1] : targets[b * NSEQ + i];
        const float4* e = (const float4*)(emb + (long)tok * NE + (c0 & (NE - 1)));
        u = pack8(e[0], e[1], 1.f);
    } else {
        u = make_uint4(0, 0, 0, 0);
    }
    *(uint4*)&g_Xh[(long)r * NH + c0] = u;
}

// weights conversion + outW fp16 with bias column
#define RSEG 3145728L
#define OUTW_ELEMS ((long)NV * NH)
#define PAD_ELEMS  ((long)NV * 32)
__global__ void conv_all(const float* __restrict__ Wih,
                         const float* __restrict__ whw,
                         const float* __restrict__ whs,
                         const float* __restrict__ wis,
                         const float* __restrict__ outW,
                         const float* __restrict__ outb) {
    long e0 = ((long)blockIdx.x * 256 + threadIdx.x) * 8;
    if (e0 < 4 * RSEG) {
        const float* src; __nv_bfloat16* dst; long off;
        if      (e0 < RSEG)     { src = Wih;  dst = g_Wih_h;    off = e0; }
        else if (e0 < 2 * RSEG) { src = whw;  dst = g_Whh_w_bf; off = e0 - RSEG; }
        else if (e0 < 3 * RSEG) { src = whs;  dst = g_Whh_s_bf; off = e0 - 2 * RSEG; }
        else                    { src = wis;  dst = g_Wih_s_bf; off = e0 - 3 * RSEG; }
        const float4* p = (const float4*)(src + off);
        *(uint4*)(dst + off) = pack8(p[0], p[1], 1.f);
    } else if (e0 < 4 * RSEG + OUTW_ELEMS) {
        long off = e0 - 4 * RSEG;
        long row = off >> 10;             // NH = 1024
        int  col = (int)(off & 1023);
        const float4* p = (const float4*)(outW + off);
        *(uint4*)(g_outW_f16 + row * KP + col) = pack8h(p[0], p[1], LOG2E);
    } else {
        long p2 = e0 - 4 * RSEG - OUTW_ELEMS;   // pad region: NV rows x 32 cols
        long row = p2 >> 5;
        int  cc  = (int)(p2 & 31);              // 0,8,16,24
        uint4 u = make_uint4(0, 0, 0, 0);
        if (cc == 0) {
            __half hb = __float2half_rn(outb[row] * LOG2E);
            u.x = (uint32_t)(*(uint16_t*)&hb);
        }
        *(uint4*)(g_outW_f16 + row * KP + 1024 + cc) = u;
    }
}

// ---------------- bf16 GEMM (gi): C = A[M,K] * B[N,K]^T, compacted rows ----------
#define BK 32
#define PADK 40

__global__ __launch_bounds__(256, 2)
void gemm_gi(const float* __restrict__ bias) {
    const long bm = blockIdx.y, bn = blockIdx.x;
    const int nvalid = g_nvalid;
    if ((int)(bm * 128) >= nvalid) return;

    const __nv_bfloat16* A = g_Xh;
    const __nv_bfloat16* B = g_Wih_h;
    float* C = g_gi;
    const int K = NH, N = H3;

    __shared__ __nv_bfloat16 As[2][128][PADK];
    __shared__ __nv_bfloat16 Bs[2][128][PADK];

    const int tid = threadIdx.x;
    const int lane = tid & 31, wid = tid >> 5;
    const int wm = wid >> 2, wn = wid & 3;
    const int KT = K / BK;

    float acc[4][4][4];
#pragma unroll
    for (int i = 0; i < 4; i++)
#pragma unroll
        for (int j = 0; j < 4; j++)
#pragma unroll
            for (int k = 0; k < 4; k++) acc[i][j][k] = 0.f;

    const int r0 = tid >> 2, kc0 = tid & 3;
    const int r1 = (tid + 256) >> 2;

    const long arow0 = (long)g_rowmap[bm * 128 + r0] * K;
    const long arow1 = (long)g_rowmap[bm * 128 + r1] * K;

    {
        cp16(&As[0][r0][kc0 * 8], A + arow0 + kc0 * 8);
        cp16(&As[0][r1][kc0 * 8], A + arow1 + kc0 * 8);
        cp16(&Bs[0][r0][kc0 * 8], B + (bn * 128 + r0) * (long)K + kc0 * 8);
        cp16(&Bs[0][r1][kc0 * 8], B + (bn * 128 + r1) * (long)K + kc0 * 8);
        cp_commit();
    }

    for (int kt = 0; kt < KT; kt++) {
        int cur = kt & 1;
        if (kt + 1 < KT) {
            int nx = cur ^ 1;
            long ko = (long)(kt + 1) * BK;
            cp16(&As[nx][r0][kc0 * 8], A + arow0 + ko + kc0 * 8);
            cp16(&As[nx][r1][kc0 * 8], A + arow1 + ko + kc0 * 8);
            cp16(&Bs[nx][r0][kc0 * 8], B + (bn * 128 + r0) * (long)K + ko + kc0 * 8);
            cp16(&Bs[nx][r1][kc0 * 8], B + (bn * 128 + r1) * (long)K + ko + kc0 * 8);
            cp_commit();
            cp_wait<1>();
        } else {
            cp_wait<0>();
        }
        __syncthreads();

#pragma unroll
        for (int ks = 0; ks < BK; ks += 16) {
            uint32_t a[4][4];
#pragma unroll
            for (int mt = 0; mt < 4; mt++) {
                int row = wm * 64 + mt * 16 + (lane & 15);
                int col = ks + ((lane >> 4) << 3);
                ldm4(a[mt][0], a[mt][1], a[mt][2], a[mt][3], &As[cur][row][col]);
            }
            uint32_t b[4][2];
#pragma unroll
            for (int np = 0; np < 2; np++) {
                int n = wn * 32 + np * 16 + ((lane >> 4) << 3) + (lane & 7);
                int col = ks + (((lane >> 3) & 1) << 3);
                uint32_t q0, q1, q2, q3;
                ldm4(q0, q1, q2, q3, &Bs[cur][n][col]);
                b[np * 2][0] = q0; b[np * 2][1] = q1;
                b[np * 2 + 1][0] = q2; b[np * 2 + 1][1] = q3;
            }
#pragma unroll
            for (int mt = 0; mt < 4; mt++)
#pragma unroll
                for (int nt = 0; nt < 4; nt++)
                    mma16816(acc[mt][nt], a[mt], b[nt]);
        }
        __syncthreads();
    }

#pragma unroll
    for (int mt = 0; mt < 4; mt++)
#pragma unroll
        for (int ri = 0; ri < 2; ri++) {
            int grow_c = (int)(bm * 128) + wm * 64 + mt * 16 + (lane >> 2) + ri * 8;
            if (grow_c >= nvalid) continue;
            long orig = g_rowmap[grow_c];
#pragma unroll
            for (int nt = 0; nt < 4; nt++) {
                int gc = (int)(bn * 128) + wn * 32 + nt * 8 + ((lane & 3) << 1);
                float v0 = acc[mt][nt][ri * 2 + 0] + bias[gc];
                float v1 = acc[mt][nt][ri * 2 + 1] + bias[gc + 1];
                *(float2*)&C[orig * N + gc] = make_float2(v0, v1);
            }
        }
}

// ---------------- vocab GEMM: 128M x 256N tiles, f16 acc, bias folded into K,
//                  lean exp2 epilogue (acc half2 -> MUFU directly) ----------------
#define VSM_A 0
#define VSM_B 20480
#define VSM_RED 61440
#define VSM_TOTAL 63488

__global__ __launch_bounds__(256, 2)
void gemm_vocab() {
    const long bm = blockIdx.x, bn = blockIdx.y;   // bm fastest: B-tile L2 reuse
    const int nvalid = g_nvalid;
    if ((int)(bm * 128) >= nvalid) return;

    extern __shared__ char dynsm[];
    __half* sA = (__half*)(dynsm + VSM_A);       // pitch 40 per 32-chunk
    __half* sB = (__half*)(dynsm + VSM_B);
    float* redbuf = (float*)(dynsm + VSM_RED);   // [128][4]

    const __half* A = g_WH_f16;
    const __half* B = g_outW_f16;

    const int tid = threadIdx.x;
    const int lane = tid & 31, wid = tid >> 5;
    const int wm = wid >> 2, wn = wid & 3;

    uint32_t acc[4][8][2];
#pragma unroll
    for (int i = 0; i < 4; i++)
#pragma unroll
        for (int j = 0; j < 8; j++) { acc[i][j][0] = 0u; acc[i][j][1] = 0u; }

    const int ar0 = tid >> 2, ar1 = (tid + 256) >> 2;
    const int akc = (tid & 3) * 8;
    const long arow0 = (long)g_rowmap[bm * 128 + ar0] * KP;
    const long arow1 = (long)g_rowmap[bm * 128 + ar1] * KP;
    long browt[4];
#pragma unroll
    for (int t = 0; t < 4; t++)
        browt[t] = (bn * 256 + ((tid + t * 256) >> 2)) * (long)KP;

    auto load_stage = [&](int st, long ko) {
        __half* dA = sA + st * (128 * PADK);
        __half* dB = sB + st * (256 * PADK);
        cp16(dA + ar0 * PADK + akc, A + arow0 + ko + akc);
        cp16(dA + ar1 * PADK + akc, A + arow1 + ko + akc);
#pragma unroll
        for (int t = 0; t < 4; t++) {
            int row = (tid + t * 256) >> 2;
            cp16(dB + row * PADK + akc, B + browt[t] + ko + akc);
        }
        cp_commit();
    };

    load_stage(0, 0);

    for (int kt = 0; kt < KTV; kt++) {
        int cur = kt & 1;
        if (kt + 1 < KTV) {
            load_stage(cur ^ 1, (long)(kt + 1) * BK);
            cp_wait<1>();
        } else {
            cp_wait<0>();
        }
        __syncthreads();

#pragma unroll
        for (int ks = 0; ks < BK; ks += 16) {
            uint32_t a[4][4];
#pragma unroll
            for (int mt = 0; mt < 4; mt++) {
                int row = wm * 64 + mt * 16 + (lane & 15);
                int col = ks + ((lane >> 4) << 3);
                ldm4(a[mt][0], a[mt][1], a[mt][2], a[mt][3],
                     sA + cur * (128 * PADK) + row * PADK + col);
            }
            uint32_t b[8][2];
#pragma unroll
            for (int np = 0; np < 4; np++) {
                int n = wn * 64 + np * 16 + ((lane >> 4) << 3) + (lane & 7);
                int col = ks + (((lane >> 3) & 1) << 3);
                uint32_t q0, q1, q2, q3;
                ldm4(q0, q1, q2, q3, sB + cur * (256 * PADK) + n * PADK + col);
                b[np * 2][0] = q0; b[np * 2][1] = q1;
                b[np * 2 + 1][0] = q2; b[np * 2 + 1][1] = q3;
            }
#pragma unroll
            for (int mt = 0; mt < 4; mt++)
#pragma unroll
                for (int nt = 0; nt < 8; nt++)
                    mma16816h(acc[mt][nt], a[mt], b[nt]);
        }
        __syncthreads();
    }

    // lean epilogue: acc half2 (log2-domain, bias included) -> ex2 directly
#pragma unroll
    for (int mt = 0; mt < 4; mt++)
#pragma unroll
        for (int ri = 0; ri < 2; ri++) {
            int rin = wm * 64 + mt * 16 + (lane >> 2) + ri * 8;
            int grow = (int)(bm * 128) + rin;
            int orig = (grow < nvalid) ? g_rowmap[grow] : -1;
            int nxt = (orig >= 0) ? g_nxt[orig] : -1;
            float s = 0.f;
#pragma unroll
            for (int nt = 0; nt < 8; nt++) {
                int gc = (int)(bn * 256) + wn * 64 + nt * 8 + ((lane & 3) << 1);
                uint32_t av = acc[mt][nt][ri];
                uint32_t eh;
                asm("ex2.approx.f16x2 %0, %1;" : "=r"(eh) : "r"(av));
                __half2 hh = *reinterpret_cast<__half2*>(&eh);
                float2 ef = __half22float2(hh);
                s += ef.x + ef.y;
                if (((unsigned)(nxt - gc)) < 2u) {
                    __half2 av2 = *reinterpret_cast<__half2*>(&av);
                    g_tgt[orig] = (nxt == gc) ? __half2float(__low2half(av2))
                                              : __half2float(__high2half(av2));
                }
            }
            s += __shfl_xor_sync(0xffffffffu, s, 1);
            s += __shfl_xor_sync(0xffffffffu, s, 2);
            if ((lane & 3) == 0) redbuf[rin * 4 + wn] = s;
        }
    __syncthreads();
    if (tid < 128) {
        int grow = (int)(bm * 128) + tid;
        if (grow < nvalid) {
            float s = redbuf[tid * 4 + 0] + redbuf[tid * 4 + 1] +
                      redbuf[tid * 4 + 2] + redbuf[tid * 4 + 3];
            atomicAdd(&g_sumexp[g_rowmap[grow]], s);
        }
    }
}

// ---------------- persistent recurrence kernel ----------------
#define SM_W 0
#define SM_H 148608
#define SM_GW 214656
#define SM_GS 217728
#define SM_EOS 220800
#define SM_TOTAL 221056
#define HPITCH 1032
#define WPITCH 1032

__device__ __forceinline__ float sigm(float x) { return 1.f / (1.f + expf(-x)); }

__device__ __forceinline__ void gridbar(int bid, int epoch) {
    __syncthreads();
    if (threadIdx.x == 0) {
        __threadfence();
        g_arrive[bid] = epoch;
    }
    if (bid == 0) {
        if (threadIdx.x < GBLK) {
            while (g_arrive[threadIdx.x] < epoch) { }
        }
        __syncthreads();
        if (threadIdx.x == 0) g_release = epoch;
    } else {
        if (threadIdx.x == 0) {
            while (g_release < epoch) { }
        }
    }
    __syncthreads();
}

__device__ __forceinline__ void loadH(__nv_bfloat16* sH, const __nv_bfloat16* src,
                                      int tid) {
    for (int i = tid; i < 32 * 128; i += 256) {
        int r = i >> 7, kc = i & 127;
        cp16(&sH[r * HPITCH + kc * 8], src + r * NH + kc * 8);
    }
    cp_commit();
    cp_wait<0>();
    __syncthreads();
}

__device__ __forceinline__ void mma_matrix(const __nv_bfloat16* sW,
                                           const __nv_bfloat16* sH,
                                           float* sPart, int mat,
                                           int lane, int wid) {
    float acc[3][2][4];
#pragma unroll
    for (int g = 0; g < 3; g++)
#pragma unroll
        for (int m = 0; m < 2; m++)
#pragma unroll
            for (int k = 0; k < 4; k++) acc[g][m][k] = 0.f;

    const int k0 = wid * 128;
#pragma unroll
    for (int ks = 0; ks < 8; ks++) {
        int kc = k0 + ks * 16;
        uint32_t a0[4], a1[4];
        int acol = kc + ((lane >> 4) << 3);
        ldm4(a0[0], a0[1], a0[2], a0[3], &sH[(lane & 15) * HPITCH + acol]);
        ldm4(a1[0], a1[1], a1[2], a1[3], &sH[(16 + (lane & 15)) * HPITCH + acol]);
#pragma unroll
        for (int g = 0; g < 3; g++) {
            uint32_t b[2];
            int bcol = kc + (((lane >> 3) & 1) << 3);
            ldm2(b[0], b[1], &sW[((mat * 3 + g) * 8 + (lane & 7)) * WPITCH + bcol]);
            mma16816(acc[g][0], a0, b);
            mma16816(acc[g][1], a1, b);
        }
    }
    __syncthreads();
#pragma unroll
    for (int g = 0; g < 3; g++)
#pragma unroll
        for (int mf = 0; mf < 2; mf++) {
            int row = mf * 16 + (lane >> 2);
            int cp = (lane & 3) * 2;
            float2* p0 = (float2*)&sPart[(((wid * 3 + g) * 32) + row) * 8 + cp];
            *p0 = make_float2(acc[g][mf][0], acc[g][mf][1]);
            float2* p1 = (float2*)&sPart[(((wid * 3 + g) * 32) + row + 8) * 8 + cp];
            *p1 = make_float2(acc[g][mf][2], acc[g][mf][3]);
        }
    __syncthreads();
}

__global__ __launch_bounds__(256, 1)
void recur_kernel(const float* __restrict__ w_bhh,
                  const float* __restrict__ s_bih,
                  const float* __restrict__ s_bhh) {
    extern __shared__ char smraw[];
    __nv_bfloat16* sW = (__nv_bfloat16*)(smraw + SM_W);
    __nv_bfloat16* sH = (__nv_bfloat16*)(smraw + SM_H);
    float* sPart = (float*)(smraw + SM_H);
    float* sGw = (float*)(smraw + SM_GW);
    float* sGs = (float*)(smraw + SM_GS);
    int* sEos = (int*)(smraw + SM_EOS);

    const int tid = threadIdx.x, bid = blockIdx.x;
    const int lane = tid & 31, wid = tid >> 5;
    const int jj0 = bid * 8;
    const int b = tid >> 3, jj = tid & 7;
    const int col = jj0 + jj;

    for (int s = tid; s < NSTEP; s += 256) sEos[s] = g_eosany[s];

    {
        const __nv_bfloat16* Wsrc[3] = {g_Whh_w_bf, g_Whh_s_bf, g_Wih_s_bf};
        for (int i = tid; i < 9 * 8 * 128; i += 256) {
            int kc = i & 127;
            int r  = (i >> 7) & 7;
            int s  = i >> 10;
            int m = s / 3, g = s - m * 3;
            cp16(&sW[(s * 8 + r) * WPITCH + kc * 8],
                 Wsrc[m] + (long)(g * 1024 + jj0 + r) * NH + kc * 8);
        }
        cp_commit();
        cp_wait<0>();
        __syncthreads();
    }

    int epoch = 0;
    for (int step = 0; step < NSTEP; step++) {
        const long gbase = (long)(step * NB + b) * H3;
        float pre_r = g_gi[gbase + col];
        float pre_z = g_gi[gbase + NH + col];
        float pre_n = g_gi[gbase + 2 * NH + col];

        const bool fast = (sEos[step] == 0);   // uniform across all blocks

        loadH(sH, g_word_h_bf, tid);
        mma_matrix(sW, sH, sPart, 0, lane, wid);
        {
            float s0 = 0.f, s1 = 0.f, s2 = 0.f;
#pragma unroll
            for (int w = 0; w < 8; w++) {
                s0 += sPart[(((w * 3 + 0) * 32) + b) * 8 + jj];
                s1 += sPart[(((w * 3 + 1) * 32) + b) * 8 + jj];
                s2 += sPart[(((w * 3 + 2) * 32) + b) * 8 + jj];
            }
            sGw[(0 * 32 + b) * 8 + jj] = s0;
            sGw[(1 * 32 + b) * 8 + jj] = s1;
            sGw[(2 * 32 + b) * 8 + jj] = s2;
        }
        __syncthreads();

        if (fast) {
            float hr = sGw[(0 * 32 + b) * 8 + jj] + w_bhh[col];
            float hz = sGw[(1 * 32 + b) * 8 + jj] + w_bhh[NH + col];
            float hn = sGw[(2 * 32 + b) * 8 + jj] + w_bhh[2 * NH + col];
            float h = g_word_h[b * NH + col];
            float r = sigm(pre_r + hr);
            float z = sigm(pre_z + hz);
            float n = tanhf(pre_n + r * hn);
            float wh = (1.f - z) * n + z * h;
            g_word_h[b * NH + col] = wh;
            g_word_h_bf[b * NH + col] = __float2bfloat16(wh);
            g_WH_f16[(long)(step * NB + b) * KP + col] = __float2half_rn(wh);
            gridbar(bid, ++epoch);
            continue;
        }

        loadH(sH, g_sent_h_bf, tid);
        mma_matrix(sW, sH, sPart, 1, lane, wid);
        {
            float s0 = 0.f, s1 = 0.f, s2 = 0.f;
#pragma unroll
            for (int w = 0; w < 8; w++) {
                s0 += sPart[(((w * 3 + 0) * 32) + b) * 8 + jj];
                s1 += sPart[(((w * 3 + 1) * 32) + b) * 8 + jj];
                s2 += sPart[(((w * 3 + 2) * 32) + b) * 8 + jj];
            }
            sGs[(0 * 32 + b) * 8 + jj] = s0 + s_bhh[col];
            sGs[(1 * 32 + b) * 8 + jj] = s1 + s_bhh[NH + col];
            sGs[(2 * 32 + b) * 8 + jj] = s2 + s_bhh[2 * NH + col];

            float hr = sGw[(0 * 32 + b) * 8 + jj] + w_bhh[col];
            float hz = sGw[(1 * 32 + b) * 8 + jj] + w_bhh[NH + col];
            float hn = sGw[(2 * 32 + b) * 8 + jj] + w_bhh[2 * NH + col];
            float h = g_word_h[b * NH + col];
            float r = sigm(pre_r + hr);
            float z = sigm(pre_z + hz);
            float n = tanhf(pre_n + r * hn);
            float wh = (1.f - z) * n + z * h;
            g_wh[b * NH + col] = wh;
            g_wh_bf[b * NH + col] = __float2bfloat16(wh);
            g_WH_f16[(long)(step * NB + b) * KP + col] = __float2half_rn(wh);
        }
        gridbar(bid, ++epoch);

        loadH(sH, g_wh_bf, tid);
        mma_matrix(sW, sH, sPart, 2, lane, wid);
        {
            float s0 = 0.f, s1 = 0.f, s2 = 0.f;
#pragma unroll
            for (int w = 0; w < 8; w++) {
                s0 += sPart[(((w * 3 + 0) * 32) + b) * 8 + jj];
                s1 += sPart[(((w * 3 + 1) * 32) + b) * 8 + jj];
                s2 += sPart[(((w * 3 + 2) * 32) + b) * 8 + jj];
            }
            float ir = s0 + s_bih[col];
            float iz = s1 + s_bih[NH + col];
            float in_ = s2 + s_bih[2 * NH + col];
            float hr = sGs[(0 * 32 + b) * 8 + jj];
            float hz = sGs[(1 * 32 + b) * 8 + jj];
            float hn = sGs[(2 * 32 + b) * 8 + jj];
            float hs = g_sent_h[b * NH + col];
            float r = sigm(ir + hr);
            float z = sigm(iz + hz);
            float n = tanhf(in_ + r * hn);
            float tmp = (1.f - z) * n + z * hs;
            float m = g_eos[step * NB + b];
            float wh = g_wh[b * NH + col];
            float ns = hs + m * (tmp - hs);
            float nw = wh + m * (tmp - wh);
            g_sent_h[b * NH + col] = ns;
            g_word_h[b * NH + col] = nw;
            g_sent_h_bf[b * NH + col] = __float2bfloat16(ns);
            g_word_h_bf[b * NH + col] = __float2bfloat16(nw);
            g_WH_f16[(long)(step * NB + b) * KP + col] = __float2half_rn(nw);
        }
        gridbar(bid, ++epoch);
    }
}

// ---------------- final reduction ----------------
__global__ void final_reduce(float* __restrict__ out) {
    __shared__ double sh[256];
    double s = 0.0;
    for (int r = threadIdx.x; r < NROWS; r += 256) {
        if (g_validf[r] != 0.f) {
            double lse = log((double)g_sumexp[r]);
            s += (double)g_tgt[r] * 0.6931471805599453 - lse;
        }
    }
    sh[threadIdx.x] = s;
    __syncthreads();
    for (int o = 128; o > 0; o >>= 1) {
        if (threadIdx.x < o) sh[threadIdx.x] += sh[threadIdx.x + o];
        __syncthreads();
    }
    if (threadIdx.x == 0) out[0] = (float)(-sh[0]);
}

// ---------------- launch ----------------
extern "C" void kernel_launch(void* const* d_in, const int* in_sizes, int n_in,
                              void* d_out, int out_size) {
    (void)in_sizes; (void)n_in; (void)out_size;
    const int*   targets     = (const int*)d_in[0];
    const int*   targets_kws = (const int*)d_in[1];
    const float* sent_state  = (const float*)d_in[2];
    const int*   targets_len = (const int*)d_in[3];
    const float* emb_W       = (const float*)d_in[4];
    const float* w_Wih       = (const float*)d_in[5];
    const float* w_Whh       = (const float*)d_in[6];
    const float* w_bih       = (const float*)d_in[7];
    const float* w_bhh       = (const float*)d_in[8];
    const float* s_Wih       = (const float*)d_in[9];
    const float* s_Whh       = (const float*)d_in[10];
    const float* s_bih       = (const float*)d_in[11];
    const float* s_bhh       = (const float*)d_in[12];
    const float* out_W       = (const float*)d_in[13];
    const float* out_b       = (const float*)d_in[14];
    float* out = (float*)d_out;

    cudaFuncSetAttribute(recur_kernel,
                         cudaFuncAttributeMaxDynamicSharedMemorySize, SM_TOTAL);
    cudaFuncSetAttribute(gemm_vocab,
                         cudaFuncAttributeMaxDynamicSharedMemorySize, VSM_TOTAL);

    // prologue (misc init + rowmap/eosany + WH pad fused: one launch)
    prologue_misc<<<NBLK_MISC + 1, 256>>>(sent_state, targets, targets_len);
    build_X<<<(MPAD * NH / 8) / 256, 256>>>(targets, targets_kws, emb_W);
    conv_all<<<(int)((4 * RSEG + OUTW_ELEMS + PAD_ELEMS) / 8 / 256), 256>>>(
        w_Wih, w_Whh, s_Whh, s_Wih, out_W, out_b);

    // gi = X @ Wih^T + bih (bf16), valid rows only (gather/scatter)
    gemm_gi<<<dim3(H3 / 128, MPAD / 128), 256>>>(w_bih);

    // persistent recurrence (63 steps, 1 launch, EOS-aware fast path)
    recur_kernel<<<GBLK, 256, SM_TOTAL>>>(w_bhh, s_bih, s_bhh);

    // vocab projection: 128x256 tiles, f16 acc, bias folded, lean exp2 epilogue
    gemm_vocab<<<dim3(MPAD / 128, NV / 256), 256, VSM_TOTAL>>>();

    final_reduce<<<1, 256>>>(out);
}